// round 2
// baseline (speedup 1.0000x reference)
#include <cuda_runtime.h>
#include <cstdint>

#define NT    49
#define DIMC  256
#define NH    8
#define HD    32
#define QSCALE 0.17677669529663687f   // 32^-0.5

// ---------------- smem layout for kernel A (float offsets) ----------------
#define X_OFF   0
#define X_STR   260                       // 260 % 32 == 4 -> conflict-free frags
#define QKV_OFF (X_OFF + NT * X_STR)      // 12740
#define QKV_STR 100                       // q[0:32) k[32:64) v[64:96)
#define S_OFF   (QKV_OFF + 56 * QKV_STR)  // 18340 (56 rows: 49 + zero pad to 56)
#define S_STR   60
#define BT_OFF  (S_OFF + 64 * S_STR)      // 22180 (64 rows so padded A-frag reads stay in-bounds)
#define W_OFF   (BT_OFF + 1352)           // 23532 (bias table 169*8)
#define W_STR   36
#define SMEMA_FLOATS (W_OFF + 96 * W_STR) // 26988
#define SMEMA_BYTES  (SMEMA_FLOATS * 4)   // 107952 B -> 2 CTAs/SM

// attention-output scratch (written by kernel A, read by kernel B)
__device__ float g_O[(size_t)4096 * NT * DIMC];

// ---------------------------------------------------------------------------
__device__ __forceinline__ float tf32r(float f) {
    unsigned u;
    asm("cvt.rna.tf32.f32 %0, %1;" : "=r"(u) : "f"(f));
    return __uint_as_float(u);
}

__device__ __forceinline__ void mma8(float* c,
                                     unsigned a0, unsigned a1, unsigned a2, unsigned a3,
                                     unsigned b0, unsigned b1) {
    asm volatile(
        "mma.sync.aligned.m16n8k8.row.col.f32.tf32.tf32.f32 "
        "{%0,%1,%2,%3}, {%4,%5,%6,%7}, {%8,%9}, {%0,%1,%2,%3};"
        : "+f"(c[0]), "+f"(c[1]), "+f"(c[2]), "+f"(c[3])
        : "r"(a0), "r"(a1), "r"(a2), "r"(a3), "r"(b0), "r"(b1));
}

// ===========================================================================
// Kernel A: fused qkv + windowed attention. One CTA per window.
// ===========================================================================
__global__ __launch_bounds__(256, 2)
void swinA(const float* __restrict__ x,
           const float* __restrict__ mask,
           const float* __restrict__ qkv_w,
           const float* __restrict__ qkv_b,
           const float* __restrict__ btab,
           int nW)
{
    extern __shared__ float sm[];
    const int tid  = threadIdx.x;
    const int lane = tid & 31;
    const int wid  = tid >> 5;
    const int b    = blockIdx.x;
    const int w    = b % nW;

    const int tr = lane >> 2;   // fragment row-within-group
    const int tc = lane & 3;    // fragment col-within-group

    // ---- stage X window (49x256) as tf32 ----
    {
        const float4* xg = (const float4*)(x + (size_t)b * NT * DIMC);
        for (int i = tid; i < NT * (DIMC / 4); i += 256) {
            int row = i >> 6, c4 = i & 63;
            float4 v = xg[row * 64 + c4];
            float* d = sm + X_OFF + row * X_STR + c4 * 4;
            d[0] = tf32r(v.x); d[1] = tf32r(v.y); d[2] = tf32r(v.z); d[3] = tf32r(v.w);
        }
    }
    // ---- stage bias table (169x8) ----
    for (int i = tid; i < 169 * 8; i += 256) sm[BT_OFF + i] = btab[i];
    // ---- zero QKV pad rows 49..55 (read as B operands by S / PV mma) ----
    for (int i = tid; i < 7 * QKV_STR; i += 256) sm[QKV_OFF + 49 * QKV_STR + i] = 0.0f;
    __syncthreads();

    for (int h = 0; h < NH; ++h) {
        // ================= QKV GEMM: C[49x96] = X @ Wh^T ==================
        // warp w: m-tile = w&3 (16 rows), n-half = w>>2 (48 cols = 6 n8-tiles)
        const int mrow  = (wid & 3) * 16;
        const int nbase = (wid >> 2) * 48;
        float acc[6][4];
        #pragma unroll
        for (int t = 0; t < 6; ++t) { acc[t][0]=acc[t][1]=acc[t][2]=acc[t][3]=0.f; }

        for (int ch = 0; ch < 8; ++ch) {        // K chunks of 32
            const int k0 = ch * 32;
            __syncthreads();                    // Wc reuse (also fences prev head's smem readers)
            // stage Wc[96x32] tf32 (rows: q/k/v slice of head h)
            #pragma unroll
            for (int t = 0; t < 3; ++t) {
                int idx = tid + t * 256;        // < 768
                int r = idx >> 3, c4 = idx & 7;
                int grow = (r >> 5) * 256 + h * 32 + (r & 31);
                float4 v = *(const float4*)(qkv_w + (size_t)grow * DIMC + k0 + c4 * 4);
                float* d = sm + W_OFF + r * W_STR + c4 * 4;
                d[0] = tf32r(v.x); d[1] = tf32r(v.y); d[2] = tf32r(v.z); d[3] = tf32r(v.w);
            }
            __syncthreads();
            #pragma unroll
            for (int kk = 0; kk < 4; ++kk) {    // 4 k8 steps
                const float* ap = sm + X_OFF + (mrow + tr) * X_STR + k0 + kk * 8 + tc;
                unsigned a0 = __float_as_uint(ap[0]);
                unsigned a1 = __float_as_uint(ap[8 * X_STR]);
                unsigned a2 = __float_as_uint(ap[4]);
                unsigned a3 = __float_as_uint(ap[8 * X_STR + 4]);
                #pragma unroll
                for (int nt = 0; nt < 6; ++nt) {
                    const float* bp = sm + W_OFF + (nbase + nt * 8 + tr) * W_STR + kk * 8 + tc;
                    mma8(acc[nt], a0, a1, a2, a3,
                         __float_as_uint(bp[0]), __float_as_uint(bp[4]));
                }
            }
        }
        // epilogue: + qkv bias, scale q, tf32 -> QKVs
        #pragma unroll
        for (int nt = 0; nt < 6; ++nt) {
            int col0 = nbase + nt * 8 + tc * 2;
            #pragma unroll
            for (int e = 0; e < 4; ++e) {
                int r = mrow + tr + ((e >> 1) ? 8 : 0);
                int c = col0 + (e & 1);
                if (r < NT) {
                    int bi = (c >> 5) * 256 + h * 32 + (c & 31);
                    float v = acc[nt][e] + __ldg(qkv_b + bi);
                    if (c < 32) v *= QSCALE;
                    sm[QKV_OFF + r * QKV_STR + c] = tf32r(v);
                }
            }
        }
        __syncthreads();

        // ================= S = Q @ K^T + bias + mask ======================
        {
            int smrow, snb, ntcnt;
            if (wid < 4) { smrow = wid * 16;       snb = 0;  ntcnt = 4; }
            else         { smrow = (wid - 4) * 16; snb = 32; ntcnt = 3; }
            float sacc[4][4];
            #pragma unroll
            for (int t = 0; t < 4; ++t) { sacc[t][0]=sacc[t][1]=sacc[t][2]=sacc[t][3]=0.f; }
            #pragma unroll
            for (int kk = 0; kk < 4; ++kk) {      // K = 32
                const float* ap = sm + QKV_OFF + (smrow + tr) * QKV_STR + kk * 8 + tc;
                unsigned a0 = __float_as_uint(ap[0]);
                unsigned a1 = __float_as_uint(ap[8 * QKV_STR]);
                unsigned a2 = __float_as_uint(ap[4]);
                unsigned a3 = __float_as_uint(ap[8 * QKV_STR + 4]);
                #pragma unroll
                for (int nt = 0; nt < 4; ++nt) {
                    if (nt < ntcnt) {
                        const float* bp = sm + QKV_OFF + (snb + nt * 8 + tr) * QKV_STR
                                          + 32 + kk * 8 + tc;
                        mma8(sacc[nt], a0, a1, a2, a3,
                             __float_as_uint(bp[0]), __float_as_uint(bp[4]));
                    }
                }
            }
            const float* mg = mask + (size_t)w * NT * NT;
            #pragma unroll
            for (int nt = 0; nt < 4; ++nt) {
                if (nt < ntcnt) {
                    int col0 = snb + nt * 8 + tc * 2;
                    #pragma unroll
                    for (int e = 0; e < 4; ++e) {
                        int r = smrow + tr + ((e >> 1) ? 8 : 0);
                        int c = col0 + (e & 1);
                        if (r < NT && c < NT) {
                            int ri = r / 7, rc = r - ri * 7;
                            int cj = c / 7, cc = c - cj * 7;
                            int rel = (ri - cj + 6) * 13 + (rc - cc + 6);
                            sm[S_OFF + r * S_STR + c] =
                                sacc[nt][e] + sm[BT_OFF + rel * 8 + h] + __ldg(mg + r * NT + c);
                        }
                    }
                }
            }
        }
        __syncthreads();

        // ================= softmax (one warp per row, striped) ============
        for (int r = wid; r < NT; r += 8) {
            float* srow = sm + S_OFF + r * S_STR;
            float v0 = srow[lane];                              // cols 0..31 all valid
            float v1 = (lane + 32 < NT) ? srow[lane + 32] : -3.4e38f;
            float m = fmaxf(v0, v1);
            #pragma unroll
            for (int o = 16; o > 0; o >>= 1) m = fmaxf(m, __shfl_xor_sync(0xffffffffu, m, o));
            float e0 = __expf(v0 - m);
            float e1 = (lane + 32 < NT) ? __expf(v1 - m) : 0.0f;
            float s = e0 + e1;
            #pragma unroll
            for (int o = 16; o > 0; o >>= 1) s += __shfl_xor_sync(0xffffffffu, s, o);
            float inv = 1.0f / s;
            srow[lane] = tf32r(e0 * inv);
            if (lane + 32 < 56) srow[lane + 32] = (lane + 32 < NT) ? tf32r(e1 * inv) : 0.0f;
        }
        __syncthreads();

        // ================= O_h = P @ V  (49x32) ===========================
        {
            const int mrow2 = (wid & 3) * 16;
            const int nb2   = (wid >> 2) * 16;
            float oacc[2][4];
            oacc[0][0]=oacc[0][1]=oacc[0][2]=oacc[0][3]=0.f;
            oacc[1][0]=oacc[1][1]=oacc[1][2]=oacc[1][3]=0.f;
            #pragma unroll
            for (int kk = 0; kk < 7; ++kk) {      // K = 56 (zero-padded)
                const float* ap = sm + S_OFF + (mrow2 + tr) * S_STR + kk * 8 + tc;
                unsigned a0 = __float_as_uint(ap[0]);
                unsigned a1 = __float_as_uint(ap[8 * S_STR]);
                unsigned a2 = __float_as_uint(ap[4]);
                unsigned a3 = __float_as_uint(ap[8 * S_STR + 4]);
                #pragma unroll
                for (int nt = 0; nt < 2; ++nt) {
                    const float* bp = sm + QKV_OFF + (kk * 8 + tc) * QKV_STR
                                      + 64 + nb2 + nt * 8 + tr;
                    mma8(oacc[nt], a0, a1, a2, a3,
                         __float_as_uint(bp[0]), __float_as_uint(bp[4 * QKV_STR]));
                }
            }
            float* og = g_O + (size_t)b * NT * DIMC + h * HD;
            #pragma unroll
            for (int nt = 0; nt < 2; ++nt) {
                int c = nb2 + nt * 8 + tc * 2;
                int r = mrow2 + tr;
                if (r < NT)     *(float2*)(og + r * DIMC + c)       = make_float2(oacc[nt][0], oacc[nt][1]);
                if (r + 8 < NT) *(float2*)(og + (r + 8) * DIMC + c) = make_float2(oacc[nt][2], oacc[nt][3]);
            }
        }
        // next head's first chunk-__syncthreads fences the smem reuse
    }
}

// ===========================================================================
// Kernel B: out = O @ proj_w^T + proj_b   (M=200704, N=256, K=256)
// ===========================================================================
__global__ __launch_bounds__(256, 2)
void projB(const float* __restrict__ pw,
           const float* __restrict__ pb,
           float* __restrict__ out)
{
    __shared__ float As[128 * 36];
    __shared__ float Bs[128 * 36];
    const int tid  = threadIdx.x;
    const int lane = tid & 31;
    const int wid  = tid >> 5;
    const int tr = lane >> 2, tc = lane & 3;
    const int mt = blockIdx.y, ntile = blockIdx.x;
    const int mw = wid & 1;          // 0/1 -> rows 0..63 / 64..127 of tile
    const int nw = wid >> 1;         // 0..3 -> 32-col strip

    float acc[4][4][4];
    #pragma unroll
    for (int mi = 0; mi < 4; ++mi)
        #pragma unroll
        for (int ni = 0; ni < 4; ++ni)
            { acc[mi][ni][0]=acc[mi][ni][1]=acc[mi][ni][2]=acc[mi][ni][3]=0.f; }

    const float* Og = g_O;
    for (int ch = 0; ch < 8; ++ch) {
        const int k0 = ch * 32;
        __syncthreads();
        #pragma unroll
        for (int t = 0; t < 4; ++t) {
            int idx = tid + t * 256;          // < 1024
            int r = idx >> 3, c4 = idx & 7;
            float4 va = *(const float4*)(Og + ((size_t)(mt * 128 + r)) * 256 + k0 + c4 * 4);
            float* da = As + r * 36 + c4 * 4;
            da[0] = tf32r(va.x); da[1] = tf32r(va.y); da[2] = tf32r(va.z); da[3] = tf32r(va.w);
            float4 vb = *(const float4*)(pw + ((size_t)(ntile * 128 + r)) * 256 + k0 + c4 * 4);
            float* db = Bs + r * 36 + c4 * 4;
            db[0] = tf32r(vb.x); db[1] = tf32r(vb.y); db[2] = tf32r(vb.z); db[3] = tf32r(vb.w);
        }
        __syncthreads();
        #pragma unroll
        for (int kk = 0; kk < 4; ++kk) {
            unsigned a[4][4], bb[4][2];
            #pragma unroll
            for (int mi = 0; mi < 4; ++mi) {
                const float* ap = As + (mw * 64 + mi * 16 + tr) * 36 + kk * 8 + tc;
                a[mi][0] = __float_as_uint(ap[0]);
                a[mi][1] = __float_as_uint(ap[8 * 36]);
                a[mi][2] = __float_as_uint(ap[4]);
                a[mi][3] = __float_as_uint(ap[8 * 36 + 4]);
            }
            #pragma unroll
            for (int ni = 0; ni < 4; ++ni) {
                const float* bp = Bs + (nw * 32 + ni * 8 + tr) * 36 + kk * 8 + tc;
                bb[ni][0] = __float_as_uint(bp[0]);
                bb[ni][1] = __float_as_uint(bp[4]);
            }
            #pragma unroll
            for (int mi = 0; mi < 4; ++mi)
                #pragma unroll
                for (int ni = 0; ni < 4; ++ni)
                    mma8(acc[mi][ni], a[mi][0], a[mi][1], a[mi][2], a[mi][3],
                         bb[ni][0], bb[ni][1]);
        }
    }
    // epilogue
    #pragma unroll
    for (int mi = 0; mi < 4; ++mi) {
        #pragma unroll
        for (int ni = 0; ni < 4; ++ni) {
            int row = mt * 128 + mw * 64 + mi * 16 + tr;
            int col = ntile * 128 + nw * 32 + ni * 8 + tc * 2;
            float b0 = __ldg(pb + col), b1 = __ldg(pb + col + 1);
            *(float2*)(out + (size_t)row * 256 + col) =
                make_float2(acc[mi][ni][0] + b0, acc[mi][ni][1] + b1);
            *(float2*)(out + (size_t)(row + 8) * 256 + col) =
                make_float2(acc[mi][ni][2] + b0, acc[mi][ni][3] + b1);
        }
    }
}

// ===========================================================================
extern "C" void kernel_launch(void* const* d_in, const int* in_sizes, int n_in,
                              void* d_out, int out_size)
{
    const float* x      = (const float*)d_in[0];
    const float* mask   = (const float*)d_in[1];
    const float* qkv_w  = (const float*)d_in[2];
    const float* qkv_b  = (const float*)d_in[3];
    const float* proj_w = (const float*)d_in[4];
    const float* proj_b = (const float*)d_in[5];
    const float* btab   = (const float*)d_in[6];
    float* out = (float*)d_out;

    const int B_ = in_sizes[0] / (NT * DIMC);   // 4096
    const int nW = in_sizes[1] / (NT * NT);     // 64

    cudaFuncSetAttribute(swinA, cudaFuncAttributeMaxDynamicSharedMemorySize, SMEMA_BYTES);

    swinA<<<B_, 256, SMEMA_BYTES>>>(x, mask, qkv_w, qkv_b, btab, nW);

    dim3 gB(2, (unsigned)((B_ * NT) / 128));    // N-tiles x M-tiles
    projB<<<gB, 256>>>(proj_w, proj_b, out);
}

// round 3
// speedup vs baseline: 1.3420x; 1.3420x over previous
#include <cuda_runtime.h>
#include <cstdint>

#define NT     49
#define DIMC   256
#define NH     8
#define HD     32
#define QSCALE 0.17677669529663687f   // 32^-0.5
#define MAXB   4096

// ------------------------- global scratch ---------------------------------
__device__ float g_Xt [(size_t)MAXB * NT * DIMC];        // tf32-rounded x      (205 MB)
__device__ float g_QKV[(size_t)MAXB * NT * 3 * DIMC];    // qkv activations     (616 MB)
__device__ float g_O  [(size_t)MAXB * NT * DIMC];        // attention output    (205 MB)
__device__ float g_Wq [3 * DIMC * DIMC];                 // tf32 qkv_w
__device__ float g_Wp [DIMC * DIMC];                     // tf32 proj_w

// ---------------------------------------------------------------------------
__device__ __forceinline__ float tf32r(float f) {
    unsigned u;
    asm("cvt.rna.tf32.f32 %0, %1;" : "=r"(u) : "f"(f));
    return __uint_as_float(u);
}

__device__ __forceinline__ void mma8(float* c,
                                     unsigned a0, unsigned a1, unsigned a2, unsigned a3,
                                     unsigned b0, unsigned b1) {
    asm volatile(
        "mma.sync.aligned.m16n8k8.row.col.f32.tf32.tf32.f32 "
        "{%0,%1,%2,%3}, {%4,%5,%6,%7}, {%8,%9}, {%0,%1,%2,%3};"
        : "+f"(c[0]), "+f"(c[1]), "+f"(c[2]), "+f"(c[3])
        : "r"(a0), "r"(a1), "r"(a2), "r"(a3), "r"(b0), "r"(b1));
}

__device__ __forceinline__ void cpa16(float* smem_dst, const float* gsrc) {
    unsigned d = (unsigned)__cvta_generic_to_shared(smem_dst);
    asm volatile("cp.async.cg.shared.global [%0], [%1], 16;" :: "r"(d), "l"(gsrc));
}

// ===========================================================================
// convert kernels: round operands to tf32 once
// ===========================================================================
__global__ void convX(const float4* __restrict__ src, float4* __restrict__ dst) {
    size_t i = (size_t)blockIdx.x * 256 + threadIdx.x;
    float4 v = src[i];
    dst[i] = make_float4(tf32r(v.x), tf32r(v.y), tf32r(v.z), tf32r(v.w));
}

__global__ void convW(const float4* __restrict__ qw, const float4* __restrict__ pw,
                      float4* __restrict__ qwt, float4* __restrict__ pwt) {
    int i = blockIdx.x * 256 + threadIdx.x;          // 65536 threads
    if (i < 49152) {
        float4 v = qw[i];
        qwt[i] = make_float4(tf32r(v.x), tf32r(v.y), tf32r(v.z), tf32r(v.w));
    } else {
        float4 v = pw[i - 49152];
        pwt[i - 49152] = make_float4(tf32r(v.x), tf32r(v.y), tf32r(v.z), tf32r(v.w));
    }
}

// ===========================================================================
// Pipelined tf32 GEMM: C[M, NC] = A[M,256] @ Bw[NC,256]^T (+bias, epilogue)
// 128x128 CTA tile, k-chunks of 32, 2-stage cp.async double buffer.
// QKVEPI: add qkv bias, scale q cols, tf32-round (store to g_QKV).
// else:   add proj bias, plain fp32 store (final output).
// ===========================================================================
#define TILE_F (128 * 36)   // floats per smem tile (36-stride padded)

__device__ __forceinline__ void load_tiles(const float* Ag, const float* Bg,
                                           float* As, float* Bs, int ch, int tid) {
    #pragma unroll
    for (int t = 0; t < 4; ++t) {
        int idx = tid + t * 256;            // < 1024
        int r = idx >> 3, c4 = idx & 7;
        cpa16(As + r * 36 + c4 * 4, Ag + (size_t)r * 256 + ch * 32 + c4 * 4);
        cpa16(Bs + r * 36 + c4 * 4, Bg + (size_t)r * 256 + ch * 32 + c4 * 4);
    }
    asm volatile("cp.async.commit_group;" ::: "memory");
}

template<bool QKVEPI, int NC>
__global__ __launch_bounds__(256, 2)
void gemmT(const float* __restrict__ A, const float* __restrict__ Bw,
           const float* __restrict__ bias, float* __restrict__ C)
{
    extern __shared__ float smg[];
    float* As = smg;                  // 2 stages x TILE_F
    float* Bs = smg + 2 * TILE_F;

    const int tid  = threadIdx.x;
    const int lane = tid & 31;
    const int wid  = tid >> 5;
    const int tr = lane >> 2, tc = lane & 3;
    const int nt = blockIdx.x, mt = blockIdx.y;
    const int mw = wid & 1;           // 64-row half
    const int nw = wid >> 1;          // 32-col strip

    const float* Ag = A  + (size_t)(mt * 128) * 256;
    const float* Bg = Bw + (size_t)(nt * 128) * 256;

    float acc[4][4][4];
    #pragma unroll
    for (int mi = 0; mi < 4; ++mi)
        #pragma unroll
        for (int ni = 0; ni < 4; ++ni)
            { acc[mi][ni][0]=acc[mi][ni][1]=acc[mi][ni][2]=acc[mi][ni][3]=0.f; }

    load_tiles(Ag, Bg, As, Bs, 0, tid);

    for (int ch = 0; ch < 8; ++ch) {
        const int buf = ch & 1;
        asm volatile("cp.async.wait_group 0;" ::: "memory");
        __syncthreads();
        if (ch < 7)
            load_tiles(Ag, Bg, As + (buf ^ 1) * TILE_F, Bs + (buf ^ 1) * TILE_F, ch + 1, tid);

        const float* Ab = As + buf * TILE_F;
        const float* Bb = Bs + buf * TILE_F;
        #pragma unroll
        for (int kk = 0; kk < 4; ++kk) {
            unsigned a[4][4], bb[4][2];
            #pragma unroll
            for (int mi = 0; mi < 4; ++mi) {
                const float* ap = Ab + (mw * 64 + mi * 16 + tr) * 36 + kk * 8 + tc;
                a[mi][0] = __float_as_uint(ap[0]);
                a[mi][1] = __float_as_uint(ap[8 * 36]);
                a[mi][2] = __float_as_uint(ap[4]);
                a[mi][3] = __float_as_uint(ap[8 * 36 + 4]);
            }
            #pragma unroll
            for (int ni = 0; ni < 4; ++ni) {
                const float* bp = Bb + (nw * 32 + ni * 8 + tr) * 36 + kk * 8 + tc;
                bb[ni][0] = __float_as_uint(bp[0]);
                bb[ni][1] = __float_as_uint(bp[4]);
            }
            #pragma unroll
            for (int mi = 0; mi < 4; ++mi)
                #pragma unroll
                for (int ni = 0; ni < 4; ++ni)
                    mma8(acc[mi][ni], a[mi][0], a[mi][1], a[mi][2], a[mi][3],
                         bb[ni][0], bb[ni][1]);
        }
    }

    // epilogue
    #pragma unroll
    for (int mi = 0; mi < 4; ++mi) {
        #pragma unroll
        for (int ni = 0; ni < 4; ++ni) {
            int row = mt * 128 + mw * 64 + mi * 16 + tr;
            int col = nt * 128 + nw * 32 + ni * 8 + tc * 2;
            float b0 = __ldg(bias + col), b1 = __ldg(bias + col + 1);
            float v00 = acc[mi][ni][0] + b0, v01 = acc[mi][ni][1] + b1;
            float v10 = acc[mi][ni][2] + b0, v11 = acc[mi][ni][3] + b1;
            if (QKVEPI) {
                if (col < 256) { v00 *= QSCALE; v01 *= QSCALE; v10 *= QSCALE; v11 *= QSCALE; }
                v00 = tf32r(v00); v01 = tf32r(v01); v10 = tf32r(v10); v11 = tf32r(v11);
            }
            *(float2*)(C + (size_t)row * NC + col)       = make_float2(v00, v01);
            *(float2*)(C + (size_t)(row + 8) * NC + col) = make_float2(v10, v11);
        }
    }
}

// ===========================================================================
// Attention kernel: CTA = (head, window). 128 threads, 4 warps.
//   S = q@k^T + bias + mask ; P = softmax(S) ; O_h = P@v
// q/k/v read from g_QKV (already tf32-rounded, q pre-scaled).
// ===========================================================================
#define AQ_OFF 0                       // [64][36]
#define AK_OFF (64 * 36)               // [56][36]
#define AV_OFF (AK_OFF + 56 * 36)      // [56][36]
#define AS_OFF (AV_OFF + 56 * 36)      // [64][60]
#define ASM_FLOATS (AS_OFF + 64 * 60)  // 10176 floats = 40704 B

__global__ __launch_bounds__(128, 4)
void attnK(const float* __restrict__ qkv,
           const float* __restrict__ mask,
           const float* __restrict__ btab,
           float* __restrict__ O, int nW)
{
    __shared__ float sm[ASM_FLOATS];
    const int tid  = threadIdx.x;
    const int lane = tid & 31;
    const int wid  = tid >> 5;
    const int h = blockIdx.x;
    const int b = blockIdx.y;
    const int w = b % nW;
    const int tr = lane >> 2, tc = lane & 3;

    // ---- stage q, k, v head slices ----
    {
        const float* base = qkv + (size_t)b * NT * 768 + h * 32;
        for (int i = tid; i < NT * 8; i += 128) {
            int r = i >> 3, c4 = i & 7;
            const float* g = base + (size_t)r * 768 + c4 * 4;
            float4 q4 = *(const float4*)(g);
            float4 k4 = *(const float4*)(g + 256);
            float4 v4 = *(const float4*)(g + 512);
            float* dq = sm + AQ_OFF + r * 36 + c4 * 4;
            dq[0]=q4.x; dq[1]=q4.y; dq[2]=q4.z; dq[3]=q4.w;
            float* dk = sm + AK_OFF + r * 36 + c4 * 4;
            dk[0]=k4.x; dk[1]=k4.y; dk[2]=k4.z; dk[3]=k4.w;
            float* dv = sm + AV_OFF + r * 36 + c4 * 4;
            dv[0]=v4.x; dv[1]=v4.y; dv[2]=v4.z; dv[3]=v4.w;
        }
        // zero v pad rows 49..55 (k-dim of PV pairs them with P pad cols)
        for (int i = tid; i < 7 * 36; i += 128) sm[AV_OFF + NT * 36 + i] = 0.f;
    }
    __syncthreads();

    const int mrow = wid * 16;

    // ---- S = q @ k^T ----
    {
        float sacc[7][4];
        #pragma unroll
        for (int t = 0; t < 7; ++t) { sacc[t][0]=sacc[t][1]=sacc[t][2]=sacc[t][3]=0.f; }
        #pragma unroll
        for (int kk = 0; kk < 4; ++kk) {
            const float* ap = sm + AQ_OFF + (mrow + tr) * 36 + kk * 8 + tc;
            unsigned a0 = __float_as_uint(ap[0]);
            unsigned a1 = __float_as_uint(ap[8 * 36]);
            unsigned a2 = __float_as_uint(ap[4]);
            unsigned a3 = __float_as_uint(ap[8 * 36 + 4]);
            #pragma unroll
            for (int nt = 0; nt < 7; ++nt) {
                const float* bp = sm + AK_OFF + (nt * 8 + tr) * 36 + kk * 8 + tc;
                mma8(sacc[nt], a0, a1, a2, a3,
                     __float_as_uint(bp[0]), __float_as_uint(bp[4]));
            }
        }
        const float* mg = mask + (size_t)w * NT * NT;
        #pragma unroll
        for (int nt = 0; nt < 7; ++nt) {
            int col0 = nt * 8 + tc * 2;
            #pragma unroll
            for (int e = 0; e < 4; ++e) {
                int r = mrow + tr + ((e >> 1) ? 8 : 0);
                int c = col0 + (e & 1);
                if (r < NT && c < NT) {
                    int ri = r / 7, rc = r - ri * 7;
                    int cj = c / 7, cc = c - cj * 7;
                    int rel = (ri - cj + 6) * 13 + (rc - cc + 6);
                    sm[AS_OFF + r * 60 + c] =
                        sacc[nt][e] + __ldg(btab + rel * 8 + h) + __ldg(mg + r * NT + c);
                }
            }
        }
    }
    __syncthreads();

    // ---- softmax (one warp per row, striped) ----
    for (int r = wid; r < NT; r += 4) {
        float* srow = sm + AS_OFF + r * 60;
        float v0 = srow[lane];
        float v1 = (lane + 32 < NT) ? srow[lane + 32] : -3.4e38f;
        float m = fmaxf(v0, v1);
        #pragma unroll
        for (int o = 16; o > 0; o >>= 1) m = fmaxf(m, __shfl_xor_sync(0xffffffffu, m, o));
        float e0 = __expf(v0 - m);
        float e1 = (lane + 32 < NT) ? __expf(v1 - m) : 0.0f;
        float s = e0 + e1;
        #pragma unroll
        for (int o = 16; o > 0; o >>= 1) s += __shfl_xor_sync(0xffffffffu, s, o);
        float inv = 1.0f / s;
        srow[lane] = tf32r(e0 * inv);
        if (lane + 32 < 56) srow[lane + 32] = (lane + 32 < NT) ? tf32r(e1 * inv) : 0.0f;
    }
    __syncthreads();

    // ---- O = P @ v ----
    {
        float oacc[4][4];
        #pragma unroll
        for (int t = 0; t < 4; ++t) { oacc[t][0]=oacc[t][1]=oacc[t][2]=oacc[t][3]=0.f; }
        #pragma unroll
        for (int kk = 0; kk < 7; ++kk) {
            const float* ap = sm + AS_OFF + (mrow + tr) * 60 + kk * 8 + tc;
            unsigned a0 = __float_as_uint(ap[0]);
            unsigned a1 = __float_as_uint(ap[8 * 60]);
            unsigned a2 = __float_as_uint(ap[4]);
            unsigned a3 = __float_as_uint(ap[8 * 60 + 4]);
            #pragma unroll
            for (int nt = 0; nt < 4; ++nt) {
                const float* bp = sm + AV_OFF + (kk * 8 + tc) * 36 + nt * 8 + tr;
                mma8(oacc[nt], a0, a1, a2, a3,
                     __float_as_uint(bp[0]), __float_as_uint(bp[4 * 36]));
            }
        }
        float* og = O + (size_t)b * NT * DIMC + h * HD;
        #pragma unroll
        for (int nt = 0; nt < 4; ++nt) {
            int c = nt * 8 + tc * 2;
            int r = mrow + tr;
            if (r < NT)
                *(float2*)(og + (size_t)r * DIMC + c) =
                    make_float2(tf32r(oacc[nt][0]), tf32r(oacc[nt][1]));
            if (r + 8 < NT)
                *(float2*)(og + (size_t)(r + 8) * DIMC + c) =
                    make_float2(tf32r(oacc[nt][2]), tf32r(oacc[nt][3]));
        }
    }
}

// ===========================================================================
extern "C" void kernel_launch(void* const* d_in, const int* in_sizes, int n_in,
                              void* d_out, int out_size)
{
    const float* x      = (const float*)d_in[0];
    const float* mask   = (const float*)d_in[1];
    const float* qkv_w  = (const float*)d_in[2];
    const float* qkv_b  = (const float*)d_in[3];
    const float* proj_w = (const float*)d_in[4];
    const float* proj_b = (const float*)d_in[5];
    const float* btab   = (const float*)d_in[6];
    float* out = (float*)d_out;

    const int B_ = in_sizes[0] / (NT * DIMC);   // 4096
    const int nW = in_sizes[1] / (NT * NT);     // 64
    const int M  = B_ * NT;                     // 200704

    float *xt, *qkvs, *os, *wq, *wp;
    cudaGetSymbolAddress((void**)&xt,   g_Xt);
    cudaGetSymbolAddress((void**)&qkvs, g_QKV);
    cudaGetSymbolAddress((void**)&os,   g_O);
    cudaGetSymbolAddress((void**)&wq,   g_Wq);
    cudaGetSymbolAddress((void**)&wp,   g_Wp);

    static int smem_set = 0;
    const int gsmem = 4 * TILE_F * 4;           // 73728 B
    if (!smem_set) {
        cudaFuncSetAttribute(gemmT<true, 768>,  cudaFuncAttributeMaxDynamicSharedMemorySize, gsmem);
        cudaFuncSetAttribute(gemmT<false, 256>, cudaFuncAttributeMaxDynamicSharedMemorySize, gsmem);
        smem_set = 1;
    }

    // 1) round operands to tf32
    convX<<<(M * DIMC) / 1024, 256>>>((const float4*)x, (float4*)xt);
    convW<<<256, 256>>>((const float4*)qkv_w, (const float4*)proj_w,
                        (float4*)wq, (float4*)wp);

    // 2) QKV = Xt @ Wq^T + b  (q pre-scaled, tf32-rounded)
    gemmT<true, 768><<<dim3(6, M / 128), 256, gsmem>>>(xt, wq, qkv_b, qkvs);

    // 3) windowed attention per (head, window)
    attnK<<<dim3(NH, B_), 128>>>(qkvs, mask, btab, os, nW);

    // 4) out = O @ Wp^T + b
    gemmT<false, 256><<<dim3(2, M / 128), 256, gsmem>>>(os, wp, proj_b, out);
}

// round 4
// speedup vs baseline: 1.7695x; 1.3186x over previous
#include <cuda_runtime.h>
#include <cstdint>

#define NT     49
#define DIMC   256
#define NH     8
#define HD     32
#define QSCALE 0.17677669529663687f   // 32^-0.5
#define MAXB   4096
#define MAXW   64

// ------------------------- global scratch ---------------------------------
__device__ float g_Xt [(size_t)MAXB * NT * DIMC];        // tf32-rounded x
__device__ float g_QKV[(size_t)MAXB * NT * 3 * DIMC];    // qkv activations
__device__ float g_O  [(size_t)MAXB * NT * DIMC];        // attention output
__device__ float g_Wq [3 * DIMC * DIMC];                 // tf32 qkv_w
__device__ float g_Wp [DIMC * DIMC];                     // tf32 proj_w
__device__ float g_BM [(size_t)MAXW * NH * NT * 56];     // bias+mask, pad=-1e30

// ---------------------------------------------------------------------------
__device__ __forceinline__ float tf32r(float f) {
    unsigned u;
    asm("cvt.rna.tf32.f32 %0, %1;" : "=r"(u) : "f"(f));
    return __uint_as_float(u);
}

__device__ __forceinline__ void mma8(float* c,
                                     unsigned a0, unsigned a1, unsigned a2, unsigned a3,
                                     unsigned b0, unsigned b1) {
    asm volatile(
        "mma.sync.aligned.m16n8k8.row.col.f32.tf32.tf32.f32 "
        "{%0,%1,%2,%3}, {%4,%5,%6,%7}, {%8,%9}, {%0,%1,%2,%3};"
        : "+f"(c[0]), "+f"(c[1]), "+f"(c[2]), "+f"(c[3])
        : "r"(a0), "r"(a1), "r"(a2), "r"(a3), "r"(b0), "r"(b1));
}

__device__ __forceinline__ void cpa16(float* smem_dst, const float* gsrc) {
    unsigned d = (unsigned)__cvta_generic_to_shared(smem_dst);
    asm volatile("cp.async.cg.shared.global [%0], [%1], 16;" :: "r"(d), "l"(gsrc));
}

// ===========================================================================
// prep kernels
// ===========================================================================
__global__ void convX(const float4* __restrict__ src, float4* __restrict__ dst) {
    size_t i = (size_t)blockIdx.x * 256 + threadIdx.x;
    float4 v = src[i];
    dst[i] = make_float4(tf32r(v.x), tf32r(v.y), tf32r(v.z), tf32r(v.w));
}

__global__ void convW(const float4* __restrict__ qw, const float4* __restrict__ pw,
                      float4* __restrict__ qwt, float4* __restrict__ pwt) {
    int i = blockIdx.x * 256 + threadIdx.x;          // 65536 threads
    if (i < 49152) {
        float4 v = qw[i];
        qwt[i] = make_float4(tf32r(v.x), tf32r(v.y), tf32r(v.z), tf32r(v.w));
    } else {
        float4 v = pw[i - 49152];
        pwt[i - 49152] = make_float4(tf32r(v.x), tf32r(v.y), tf32r(v.z), tf32r(v.w));
    }
}

// BM[w][h][r][c56] = bias_gather(r,c) + mask[w][r][c]  (c<49), else -1e30
__global__ void prepBM(const float* __restrict__ mask,
                       const float* __restrict__ btab) {
    const int h = blockIdx.x, w = blockIdx.y;
    float* dst = g_BM + ((size_t)(w * NH + h) * NT) * 56;
    const float* mg = mask + (size_t)w * NT * NT;
    for (int i = threadIdx.x; i < NT * 56; i += 256) {
        int r = i / 56, c = i - r * 56;
        float v = -1e30f;
        if (c < NT) {
            int ri = r / 7, rc = r - ri * 7;
            int cj = c / 7, cc = c - cj * 7;
            int rel = (ri - cj + 6) * 13 + (rc - cc + 6);
            v = __ldg(btab + rel * 8 + h) + __ldg(mg + r * NT + c);
        }
        dst[i] = v;
    }
}

// ===========================================================================
// Pipelined tf32 GEMM: C[M, NC] = A[M,256] @ Bw[NC,256]^T (+bias, epilogue)
// ===========================================================================
#define TILE_F (128 * 36)

__device__ __forceinline__ void load_tiles(const float* Ag, const float* Bg,
                                           float* As, float* Bs, int ch, int tid) {
    #pragma unroll
    for (int t = 0; t < 4; ++t) {
        int idx = tid + t * 256;
        int r = idx >> 3, c4 = idx & 7;
        cpa16(As + r * 36 + c4 * 4, Ag + (size_t)r * 256 + ch * 32 + c4 * 4);
        cpa16(Bs + r * 36 + c4 * 4, Bg + (size_t)r * 256 + ch * 32 + c4 * 4);
    }
    asm volatile("cp.async.commit_group;" ::: "memory");
}

template<bool QKVEPI, int NC>
__global__ __launch_bounds__(256, 2)
void gemmT(const float* __restrict__ A, const float* __restrict__ Bw,
           const float* __restrict__ bias, float* __restrict__ C)
{
    extern __shared__ float smg[];
    float* As = smg;
    float* Bs = smg + 2 * TILE_F;

    const int tid  = threadIdx.x;
    const int lane = tid & 31;
    const int wid  = tid >> 5;
    const int tr = lane >> 2, tc = lane & 3;
    const int nt = blockIdx.x, mt = blockIdx.y;
    const int mw = wid & 1;
    const int nw = wid >> 1;

    const float* Ag = A  + (size_t)(mt * 128) * 256;
    const float* Bg = Bw + (size_t)(nt * 128) * 256;

    float acc[4][4][4];
    #pragma unroll
    for (int mi = 0; mi < 4; ++mi)
        #pragma unroll
        for (int ni = 0; ni < 4; ++ni)
            { acc[mi][ni][0]=acc[mi][ni][1]=acc[mi][ni][2]=acc[mi][ni][3]=0.f; }

    load_tiles(Ag, Bg, As, Bs, 0, tid);

    for (int ch = 0; ch < 8; ++ch) {
        const int buf = ch & 1;
        asm volatile("cp.async.wait_group 0;" ::: "memory");
        __syncthreads();
        if (ch < 7)
            load_tiles(Ag, Bg, As + (buf ^ 1) * TILE_F, Bs + (buf ^ 1) * TILE_F, ch + 1, tid);

        const float* Ab = As + buf * TILE_F;
        const float* Bb = Bs + buf * TILE_F;
        #pragma unroll
        for (int kk = 0; kk < 4; ++kk) {
            unsigned a[4][4], bb[4][2];
            #pragma unroll
            for (int mi = 0; mi < 4; ++mi) {
                const float* ap = Ab + (mw * 64 + mi * 16 + tr) * 36 + kk * 8 + tc;
                a[mi][0] = __float_as_uint(ap[0]);
                a[mi][1] = __float_as_uint(ap[8 * 36]);
                a[mi][2] = __float_as_uint(ap[4]);
                a[mi][3] = __float_as_uint(ap[8 * 36 + 4]);
            }
            #pragma unroll
            for (int ni = 0; ni < 4; ++ni) {
                const float* bp = Bb + (nw * 32 + ni * 8 + tr) * 36 + kk * 8 + tc;
                bb[ni][0] = __float_as_uint(bp[0]);
                bb[ni][1] = __float_as_uint(bp[4]);
            }
            #pragma unroll
            for (int mi = 0; mi < 4; ++mi)
                #pragma unroll
                for (int ni = 0; ni < 4; ++ni)
                    mma8(acc[mi][ni], a[mi][0], a[mi][1], a[mi][2], a[mi][3],
                         bb[ni][0], bb[ni][1]);
        }
    }

    #pragma unroll
    for (int mi = 0; mi < 4; ++mi) {
        #pragma unroll
        for (int ni = 0; ni < 4; ++ni) {
            int row = mt * 128 + mw * 64 + mi * 16 + tr;
            int col = nt * 128 + nw * 32 + ni * 8 + tc * 2;
            float b0 = __ldg(bias + col), b1 = __ldg(bias + col + 1);
            float v00 = acc[mi][ni][0] + b0, v01 = acc[mi][ni][1] + b1;
            float v10 = acc[mi][ni][2] + b0, v11 = acc[mi][ni][3] + b1;
            if (QKVEPI) {
                if (col < 256) { v00 *= QSCALE; v01 *= QSCALE; v10 *= QSCALE; v11 *= QSCALE; }
                v00 = tf32r(v00); v01 = tf32r(v01); v10 = tf32r(v10); v11 = tf32r(v11);
            }
            *(float2*)(C + (size_t)row * NC + col)       = make_float2(v00, v01);
            *(float2*)(C + (size_t)(row + 8) * NC + col) = make_float2(v10, v11);
        }
    }
}

// ===========================================================================
// Attention kernel v2: CTA = (head, window), 128 threads.
// Register softmax (lane-quad shfl), BM table, single __syncthreads.
// ===========================================================================
#define AQ 0                      // [64][36]
#define AK (64 * 36)              // [56][36]
#define AV (AK + 56 * 36)         // [56][36]
#define AP (AV + 56 * 36)         // [64][60]
#define ASMF (AP + 64 * 60)       // 10176 floats = 40704 B

__global__ __launch_bounds__(128, 5)
void attnK(const float* __restrict__ qkv, float* __restrict__ O, int nW)
{
    __shared__ float sm[ASMF];
    const int tid  = threadIdx.x;
    const int lane = tid & 31;
    const int wid  = tid >> 5;
    const int h = blockIdx.x;
    const int b = blockIdx.y;
    const int w = b % nW;
    const int tr = lane >> 2, tc = lane & 3;

    // zero K/V pad rows 49..55 (K pads feed S cols >=49; V pads pair with P=0)
    for (int i = tid; i < 7 * 36; i += 128) {
        sm[AK + NT * 36 + i] = 0.f;
        sm[AV + NT * 36 + i] = 0.f;
    }
    // stage q/k/v head slices via cp.async
    {
        const float* base = qkv + (size_t)b * NT * 768 + h * 32;
        for (int i = tid; i < NT * 8; i += 128) {
            int r = i >> 3, c4 = i & 7;
            const float* g = base + (size_t)r * 768 + c4 * 4;
            cpa16(sm + AQ + r * 36 + c4 * 4, g);
            cpa16(sm + AK + r * 36 + c4 * 4, g + 256);
            cpa16(sm + AV + r * 36 + c4 * 4, g + 512);
        }
        asm volatile("cp.async.commit_group;" ::: "memory");
        asm volatile("cp.async.wait_group 0;" ::: "memory");
    }
    __syncthreads();

    const int mrow = wid * 16;

    // ---- S = q @ k^T (q pre-scaled) ----
    float sacc[7][4];
    #pragma unroll
    for (int t = 0; t < 7; ++t) { sacc[t][0]=sacc[t][1]=sacc[t][2]=sacc[t][3]=0.f; }
    #pragma unroll
    for (int kk = 0; kk < 4; ++kk) {
        const float* ap = sm + AQ + (mrow + tr) * 36 + kk * 8 + tc;
        unsigned a0 = __float_as_uint(ap[0]);
        unsigned a1 = __float_as_uint(ap[8 * 36]);
        unsigned a2 = __float_as_uint(ap[4]);
        unsigned a3 = __float_as_uint(ap[8 * 36 + 4]);
        #pragma unroll
        for (int nt = 0; nt < 7; ++nt) {
            const float* bp = sm + AK + (nt * 8 + tr) * 36 + kk * 8 + tc;
            mma8(sacc[nt], a0, a1, a2, a3,
                 __float_as_uint(bp[0]), __float_as_uint(bp[4]));
        }
    }

    // ---- register softmax + normalized-P smem write ----
    {
        const float* bmb = g_BM + ((size_t)(w * NH + h) * NT) * 56;
        #pragma unroll
        for (int g = 0; g < 2; ++g) {
            int r  = mrow + tr + 8 * g;
            int rb = (r < NT) ? r : NT - 1;          // clamp garbage rows in-bounds
            const float* bmr = bmb + (size_t)rb * 56 + tc * 2;
            float v[7][2];
            float m = -3.4e38f;
            #pragma unroll
            for (int nt = 0; nt < 7; ++nt) {
                float2 bm2 = *(const float2*)(bmr + nt * 8);
                v[nt][0] = sacc[nt][2 * g]     + bm2.x;
                v[nt][1] = sacc[nt][2 * g + 1] + bm2.y;
                m = fmaxf(m, fmaxf(v[nt][0], v[nt][1]));
            }
            m = fmaxf(m, __shfl_xor_sync(0xffffffffu, m, 1));
            m = fmaxf(m, __shfl_xor_sync(0xffffffffu, m, 2));
            float s = 0.f;
            #pragma unroll
            for (int nt = 0; nt < 7; ++nt) {
                v[nt][0] = __expf(v[nt][0] - m);
                v[nt][1] = __expf(v[nt][1] - m);
                s += v[nt][0] + v[nt][1];
            }
            s += __shfl_xor_sync(0xffffffffu, s, 1);
            s += __shfl_xor_sync(0xffffffffu, s, 2);
            float inv = 1.0f / s;
            float* pr = sm + AP + r * 60 + tc * 2;
            #pragma unroll
            for (int nt = 0; nt < 7; ++nt)
                *(float2*)(pr + nt * 8) =
                    make_float2(tf32r(v[nt][0] * inv), tf32r(v[nt][1] * inv));
        }
    }
    __syncwarp();   // P rows for this warp's O tile were written by this warp

    // ---- O = P @ v ----
    {
        float oacc[4][4];
        #pragma unroll
        for (int t = 0; t < 4; ++t) { oacc[t][0]=oacc[t][1]=oacc[t][2]=oacc[t][3]=0.f; }
        #pragma unroll
        for (int kk = 0; kk < 7; ++kk) {
            const float* ap = sm + AP + (mrow + tr) * 60 + kk * 8 + tc;
            unsigned a0 = __float_as_uint(ap[0]);
            unsigned a1 = __float_as_uint(ap[8 * 60]);
            unsigned a2 = __float_as_uint(ap[4]);
            unsigned a3 = __float_as_uint(ap[8 * 60 + 4]);
            #pragma unroll
            for (int nt = 0; nt < 4; ++nt) {
                const float* bp = sm + AV + (kk * 8 + tc) * 36 + nt * 8 + tr;
                mma8(oacc[nt], a0, a1, a2, a3,
                     __float_as_uint(bp[0]), __float_as_uint(bp[4 * 36]));
            }
        }
        float* og = O + (size_t)b * NT * DIMC + h * HD;
        #pragma unroll
        for (int nt = 0; nt < 4; ++nt) {
            int c = nt * 8 + tc * 2;
            int r = mrow + tr;
            if (r < NT)
                *(float2*)(og + (size_t)r * DIMC + c) =
                    make_float2(tf32r(oacc[nt][0]), tf32r(oacc[nt][1]));
            if (r + 8 < NT)
                *(float2*)(og + (size_t)(r + 8) * DIMC + c) =
                    make_float2(tf32r(oacc[nt][2]), tf32r(oacc[nt][3]));
        }
    }
}

// ===========================================================================
extern "C" void kernel_launch(void* const* d_in, const int* in_sizes, int n_in,
                              void* d_out, int out_size)
{
    const float* x      = (const float*)d_in[0];
    const float* mask   = (const float*)d_in[1];
    const float* qkv_w  = (const float*)d_in[2];
    const float* qkv_b  = (const float*)d_in[3];
    const float* proj_w = (const float*)d_in[4];
    const float* proj_b = (const float*)d_in[5];
    const float* btab   = (const float*)d_in[6];
    float* out = (float*)d_out;

    const int B_ = in_sizes[0] / (NT * DIMC);   // 4096
    const int nW = in_sizes[1] / (NT * NT);     // 64
    const int M  = B_ * NT;                     // 200704

    float *xt, *qkvs, *os, *wq, *wp;
    cudaGetSymbolAddress((void**)&xt,   g_Xt);
    cudaGetSymbolAddress((void**)&qkvs, g_QKV);
    cudaGetSymbolAddress((void**)&os,   g_O);
    cudaGetSymbolAddress((void**)&wq,   g_Wq);
    cudaGetSymbolAddress((void**)&wp,   g_Wp);

    static int smem_set = 0;
    const int gsmem = 4 * TILE_F * 4;           // 73728 B
    if (!smem_set) {
        cudaFuncSetAttribute(gemmT<true, 768>,  cudaFuncAttributeMaxDynamicSharedMemorySize, gsmem);
        cudaFuncSetAttribute(gemmT<false, 256>, cudaFuncAttributeMaxDynamicSharedMemorySize, gsmem);
        smem_set = 1;
    }

    // 1) operand prep (tf32 rounding) + combined bias/mask table
    convX<<<(M * DIMC) / 1024, 256>>>((const float4*)x, (float4*)xt);
    convW<<<256, 256>>>((const float4*)qkv_w, (const float4*)proj_w,
                        (float4*)wq, (float4*)wp);
    prepBM<<<dim3(NH, nW), 256>>>(mask, btab);

    // 2) QKV = Xt @ Wq^T + b  (q pre-scaled, tf32-rounded)
    gemmT<true, 768><<<dim3(6, M / 128), 256, gsmem>>>(xt, wq, qkv_b, qkvs);

    // 3) windowed attention per (head, window)
    attnK<<<dim3(NH, B_), 128>>>(qkvs, os, nW);

    // 4) out = O @ Wp^T + b
    gemmT<false, 256><<<dim3(2, M / 128), 256, gsmem>>>(os, wp, proj_b, out);
}

// round 6
// speedup vs baseline: 2.9915x; 1.6906x over previous
#include <cuda_runtime.h>
#include <cuda_fp16.h>
#include <cstdint>

#define NT     49
#define DIMC   256
#define NH     8
#define HD     32
#define QSCALE 0.17677669529663687f   // 32^-0.5
#define MAXB   4096
#define MAXW   64

// ------------------------- global scratch ---------------------------------
__device__ __half g_Xh [(size_t)MAXB * NT * DIMC];        // fp16 x
__device__ __half g_QKV[(size_t)MAXB * NT * 3 * DIMC];    // fp16 qkv activations
__device__ __half g_Oh [(size_t)MAXB * NT * DIMC];        // fp16 attention out
__device__ __half g_Wq [3 * DIMC * DIMC];                 // fp16 qkv_w
__device__ __half g_Wp [DIMC * DIMC];                     // fp16 proj_w
__device__ float  g_BM [(size_t)MAXW * NH * NT * 56];     // bias+mask, pad=-1e30

// ---------------------------------------------------------------------------
__device__ __forceinline__ void cpa16(void* smem_dst, const void* gsrc) {
    unsigned d = (unsigned)__cvta_generic_to_shared(smem_dst);
    asm volatile("cp.async.cg.shared.global [%0], [%1], 16;" :: "r"(d), "l"(gsrc));
}

__device__ __forceinline__ void mma16(float* c,
                                      uint32_t a0, uint32_t a1, uint32_t a2, uint32_t a3,
                                      uint32_t b0, uint32_t b1) {
    asm volatile(
        "mma.sync.aligned.m16n8k16.row.col.f32.f16.f16.f32 "
        "{%0,%1,%2,%3}, {%4,%5,%6,%7}, {%8,%9}, {%0,%1,%2,%3};"
        : "+f"(c[0]), "+f"(c[1]), "+f"(c[2]), "+f"(c[3])
        : "r"(a0), "r"(a1), "r"(a2), "r"(a3), "r"(b0), "r"(b1));
}

__device__ __forceinline__ void ldsm4(uint32_t& r0, uint32_t& r1,
                                      uint32_t& r2, uint32_t& r3, uint32_t addr) {
    asm volatile("ldmatrix.sync.aligned.m8n8.x4.shared.b16 {%0,%1,%2,%3}, [%4];"
                 : "=r"(r0), "=r"(r1), "=r"(r2), "=r"(r3) : "r"(addr));
}

__device__ __forceinline__ void ldsm4t(uint32_t& r0, uint32_t& r1,
                                       uint32_t& r2, uint32_t& r3, uint32_t addr) {
    asm volatile("ldmatrix.sync.aligned.m8n8.x4.trans.shared.b16 {%0,%1,%2,%3}, [%4];"
                 : "=r"(r0), "=r"(r1), "=r"(r2), "=r"(r3) : "r"(addr));
}

// ===========================================================================
// prep kernels: fp32 -> fp16 conversion + bias/mask table
// ===========================================================================
__global__ void convX(const float4* __restrict__ src, __half2* __restrict__ dst) {
    size_t i = (size_t)blockIdx.x * 256 + threadIdx.x;
    float4 v = src[i];
    dst[2 * i]     = __floats2half2_rn(v.x, v.y);
    dst[2 * i + 1] = __floats2half2_rn(v.z, v.w);
}

__global__ void convW(const float4* __restrict__ qw, const float4* __restrict__ pw,
                      __half2* __restrict__ qwt, __half2* __restrict__ pwt) {
    int i = blockIdx.x * 256 + threadIdx.x;          // 65536 threads
    if (i < 49152) {
        float4 v = qw[i];
        qwt[2 * i]     = __floats2half2_rn(v.x, v.y);
        qwt[2 * i + 1] = __floats2half2_rn(v.z, v.w);
    } else {
        int j = i - 49152;
        float4 v = pw[j];
        pwt[2 * j]     = __floats2half2_rn(v.x, v.y);
        pwt[2 * j + 1] = __floats2half2_rn(v.z, v.w);
    }
}

__global__ void prepBM(const float* __restrict__ mask,
                       const float* __restrict__ btab) {
    const int h = blockIdx.x, w = blockIdx.y;
    float* dst = g_BM + ((size_t)(w * NH + h) * NT) * 56;
    const float* mg = mask + (size_t)w * NT * NT;
    for (int i = threadIdx.x; i < NT * 56; i += 256) {
        int r = i / 56, c = i - r * 56;
        float v = -1e30f;
        if (c < NT) {
            int ri = r / 7, rc = r - ri * 7;
            int cj = c / 7, cc = c - cj * 7;
            int rel = (ri - cj + 6) * 13 + (rc - cc + 6);
            v = __ldg(btab + rel * 8 + h) + __ldg(mg + r * NT + c);
        }
        dst[i] = v;
    }
}

// ===========================================================================
// fp16 GEMM: C[M,NC] = A[M,256] @ Bw[NC,256]^T (+bias).
// 128x128 CTA tile, K chunks of 64 halves, 2-stage cp.async, ldmatrix+HMMA.
// ===========================================================================
#define GSTR    72                 // padded smem row stride (halves)
#define GTILE_H (128 * GSTR)       // halves per tile buffer
#define GSMEMH  (4 * GTILE_H * 2)  // bytes: 2 stages x (A + B) = 73728

__device__ __forceinline__ void stageH(__half* st, const __half* Ag, const __half* Bg,
                                       int ch, int tid) {
    #pragma unroll
    for (int t = 0; t < 8; ++t) {
        int idx = tid + t * 256;            // 0..2047
        int tensor = idx >> 10;             // 0 = A, 1 = B
        int r  = (idx >> 3) & 127;
        int c8 = idx & 7;
        const __half* src = (tensor ? Bg : Ag) + (size_t)r * 256 + ch * 64 + c8 * 8;
        cpa16(st + tensor * GTILE_H + r * GSTR + c8 * 8, src);
    }
    asm volatile("cp.async.commit_group;" ::: "memory");
}

template<bool QKVEPI, int NC>
__global__ __launch_bounds__(256, 2)
void gemmH(const __half* __restrict__ A, const __half* __restrict__ Bw,
           const float* __restrict__ bias, void* __restrict__ Cout)
{
    extern __shared__ __half smh[];
    const int tid  = threadIdx.x;
    const int lane = tid & 31;
    const int wid  = tid >> 5;
    const int tr = lane >> 2, tc = lane & 3;
    const int nt = blockIdx.x, mt = blockIdx.y;
    const int mw = wid & 1;        // 64-row half of tile
    const int nw = wid >> 1;       // 32-col strip

    const __half* Ag = A  + (size_t)(mt * 128) * 256;
    const __half* Bg = Bw + (size_t)(nt * 128) * 256;

    // ldmatrix lane-address components
    const int g8   = lane >> 3;
    const int arow = (lane & 7) + ((g8 & 1) << 3);
    const int acol = (g8 >> 1) << 3;
    const int brow = (lane & 7) + ((g8 >> 1) << 3);
    const int bcol = (g8 & 1) << 3;

    const uint32_t sb = (uint32_t)__cvta_generic_to_shared(smh);

    float acc[4][4][4];
    #pragma unroll
    for (int mi = 0; mi < 4; ++mi)
        #pragma unroll
        for (int ni = 0; ni < 4; ++ni)
            { acc[mi][ni][0]=acc[mi][ni][1]=acc[mi][ni][2]=acc[mi][ni][3]=0.f; }

    stageH(smh,               Ag, Bg, 0, tid);
    stageH(smh + 2 * GTILE_H, Ag, Bg, 1, tid);

    for (int ch = 0; ch < 4; ++ch) {
        const int buf = ch & 1;
        if (ch < 3) asm volatile("cp.async.wait_group 1;" ::: "memory");
        else        asm volatile("cp.async.wait_group 0;" ::: "memory");
        __syncthreads();

        const uint32_t Ab = sb + (buf * 2) * GTILE_H * 2;
        const uint32_t Bb = Ab + GTILE_H * 2;
        #pragma unroll
        for (int kk = 0; kk < 4; ++kk) {
            uint32_t a[4][4];
            #pragma unroll
            for (int mi = 0; mi < 4; ++mi)
                ldsm4(a[mi][0], a[mi][1], a[mi][2], a[mi][3],
                      Ab + (uint32_t)((mw * 64 + mi * 16 + arow) * GSTR + kk * 16 + acol) * 2);
            uint32_t bf[4][2];
            #pragma unroll
            for (int p = 0; p < 2; ++p) {
                uint32_t r0, r1, r2, r3;
                ldsm4(r0, r1, r2, r3,
                      Bb + (uint32_t)((nw * 32 + p * 16 + brow) * GSTR + kk * 16 + bcol) * 2);
                bf[2 * p][0] = r0; bf[2 * p][1] = r1;
                bf[2 * p + 1][0] = r2; bf[2 * p + 1][1] = r3;
            }
            #pragma unroll
            for (int mi = 0; mi < 4; ++mi)
                #pragma unroll
                for (int ni = 0; ni < 4; ++ni)
                    mma16(acc[mi][ni], a[mi][0], a[mi][1], a[mi][2], a[mi][3],
                          bf[ni][0], bf[ni][1]);
        }

        if (ch < 2) {
            __syncthreads();
            stageH(smh + (buf * 2) * GTILE_H, Ag, Bg, ch + 2, tid);
        }
    }

    // epilogue
    #pragma unroll
    for (int mi = 0; mi < 4; ++mi) {
        #pragma unroll
        for (int ni = 0; ni < 4; ++ni) {
            int row = mt * 128 + mw * 64 + mi * 16 + tr;
            int col = nt * 128 + nw * 32 + ni * 8 + tc * 2;
            float b0 = __ldg(bias + col), b1 = __ldg(bias + col + 1);
            float v00 = acc[mi][ni][0] + b0, v01 = acc[mi][ni][1] + b1;
            float v10 = acc[mi][ni][2] + b0, v11 = acc[mi][ni][3] + b1;
            if (QKVEPI) {
                if (col < 256) { v00 *= QSCALE; v01 *= QSCALE; v10 *= QSCALE; v11 *= QSCALE; }
                __half* Ch = (__half*)Cout;
                *(__half2*)(Ch + (size_t)row * NC + col)       = __floats2half2_rn(v00, v01);
                *(__half2*)(Ch + (size_t)(row + 8) * NC + col) = __floats2half2_rn(v10, v11);
            } else {
                float* Cf = (float*)Cout;
                *(float2*)(Cf + (size_t)row * NC + col)       = make_float2(v00, v01);
                *(float2*)(Cf + (size_t)(row + 8) * NC + col) = make_float2(v10, v11);
            }
        }
    }
}

// ===========================================================================
// fp16 attention: CTA = (head, window), 128 threads, ldmatrix + HMMA.
// ===========================================================================
#define AQS 0                      // [64][40] halves
#define AKS (64 * 40)
#define AVS (2 * 64 * 40)
#define APS (3 * 64 * 40)          // P: [64][72]
#define ATT_H (APS + 64 * 72)      // 12288 halves = 24576 B

__global__ __launch_bounds__(128, 5)
void attnH(const __half* __restrict__ qkv, __half* __restrict__ O, int nW)
{
    __shared__ __half sh[ATT_H];
    const int tid  = threadIdx.x;
    const int lane = tid & 31;
    const int wid  = tid >> 5;
    const int h = blockIdx.x;
    const int b = blockIdx.y;
    const int w = b % nW;
    const int tr = lane >> 2, tc = lane & 3;
    const uint32_t sb = (uint32_t)__cvta_generic_to_shared(sh);

    // zero K,V pad rows 49..63 (600 halves each, contiguous)
    {
        uint32_t* zk = (uint32_t*)(sh + AKS + NT * 40);
        uint32_t* zv = (uint32_t*)(sh + AVS + NT * 40);
        for (int i = tid; i < 300; i += 128) { zk[i] = 0u; zv[i] = 0u; }
    }
    // stage q/k/v head slices (49 rows x 32 halves each)
    {
        const __half* base = qkv + (size_t)b * NT * 768 + h * 32;
        for (int i = tid; i < NT * 4; i += 128) {
            int r = i >> 2, c = (i & 3) * 8;
            const __half* g = base + (size_t)r * 768 + c;
            cpa16(sh + AQS + r * 40 + c, g);
            cpa16(sh + AKS + r * 40 + c, g + 256);
            cpa16(sh + AVS + r * 40 + c, g + 512);
        }
        asm volatile("cp.async.commit_group;" ::: "memory");
        asm volatile("cp.async.wait_group 0;" ::: "memory");
    }
    __syncthreads();

    const int mrow = wid * 16;
    const int g8   = lane >> 3;
    const int arow = (lane & 7) + ((g8 & 1) << 3);
    const int acol = (g8 >> 1) << 3;
    const int brow = (lane & 7) + ((g8 >> 1) << 3);
    const int bcol = (g8 & 1) << 3;

    // ---- S = q @ k^T  (q pre-scaled; K=32 -> 2 k16 steps; 7 n-tiles) ----
    float sacc[7][4];
    #pragma unroll
    for (int t = 0; t < 7; ++t) { sacc[t][0]=sacc[t][1]=sacc[t][2]=sacc[t][3]=0.f; }
    {
        uint32_t qa[2][4];
        #pragma unroll
        for (int kk = 0; kk < 2; ++kk)
            ldsm4(qa[kk][0], qa[kk][1], qa[kk][2], qa[kk][3],
                  sb + (uint32_t)((AQS + (mrow + arow) * 40 + kk * 16 + acol)) * 2);
        #pragma unroll
        for (int kk = 0; kk < 2; ++kk) {
            #pragma unroll
            for (int p = 0; p < 4; ++p) {
                uint32_t r0, r1, r2, r3;
                ldsm4(r0, r1, r2, r3,
                      sb + (uint32_t)((AKS + (p * 16 + brow) * 40 + kk * 16 + bcol)) * 2);
                mma16(sacc[2 * p], qa[kk][0], qa[kk][1], qa[kk][2], qa[kk][3], r0, r1);
                if (p < 3)
                    mma16(sacc[2 * p + 1], qa[kk][0], qa[kk][1], qa[kk][2], qa[kk][3], r2, r3);
            }
        }
    }

    // ---- register softmax + P (half) smem write; zero pad cols 56..63 ----
    {
        const float* bmb = g_BM + ((size_t)(w * NH + h) * NT) * 56;
        #pragma unroll
        for (int g2 = 0; g2 < 2; ++g2) {
            int r  = mrow + tr + 8 * g2;
            int rb = (r < NT) ? r : NT - 1;
            const float* bmr = bmb + (size_t)rb * 56 + tc * 2;
            float v[7][2];
            float m = -3.4e38f;
            #pragma unroll
            for (int nt = 0; nt < 7; ++nt) {
                float2 bm2 = *(const float2*)(bmr + nt * 8);
                v[nt][0] = sacc[nt][2 * g2]     + bm2.x;
                v[nt][1] = sacc[nt][2 * g2 + 1] + bm2.y;
                m = fmaxf(m, fmaxf(v[nt][0], v[nt][1]));
            }
            m = fmaxf(m, __shfl_xor_sync(0xffffffffu, m, 1));
            m = fmaxf(m, __shfl_xor_sync(0xffffffffu, m, 2));
            float s = 0.f;
            #pragma unroll
            for (int nt = 0; nt < 7; ++nt) {
                v[nt][0] = __expf(v[nt][0] - m);
                v[nt][1] = __expf(v[nt][1] - m);
                s += v[nt][0] + v[nt][1];
            }
            s += __shfl_xor_sync(0xffffffffu, s, 1);
            s += __shfl_xor_sync(0xffffffffu, s, 2);
            float inv = 1.0f / s;
            __half* pr = sh + APS + r * 72 + tc * 2;
            #pragma unroll
            for (int nt = 0; nt < 7; ++nt)
                *(__half2*)(pr + nt * 8) = __floats2half2_rn(v[nt][0] * inv, v[nt][1] * inv);
            *(__half2*)(pr + 56) = __float2half2_rn(0.f);   // cols 56..63
        }
    }
    __syncwarp();   // this warp's PV reads only its own P rows

    // ---- O = P @ v  (K=64 padded -> 4 k16 steps; V via trans ldmatrix) ----
    {
        float oacc[4][4];
        #pragma unroll
        for (int t = 0; t < 4; ++t) { oacc[t][0]=oacc[t][1]=oacc[t][2]=oacc[t][3]=0.f; }
        #pragma unroll
        for (int kk = 0; kk < 4; ++kk) {
            uint32_t pa0, pa1, pa2, pa3;
            ldsm4(pa0, pa1, pa2, pa3,
                  sb + (uint32_t)((APS + (mrow + arow) * 72 + kk * 16 + acol)) * 2);
            #pragma unroll
            for (int q = 0; q < 2; ++q) {
                uint32_t r0, r1, r2, r3;
                // trans: addresses = V rows (kv), cols = head-dim
                ldsm4t(r0, r1, r2, r3,
                       sb + (uint32_t)((AVS + (kk * 16 + (lane & 7) + ((g8 & 1) << 3)) * 40
                                        + q * 16 + ((g8 >> 1) << 3))) * 2);
                mma16(oacc[2 * q],     pa0, pa1, pa2, pa3, r0, r1);
                mma16(oacc[2 * q + 1], pa0, pa1, pa2, pa3, r2, r3);
            }
        }
        __half* og = O + (size_t)b * NT * DIMC + h * HD;
        #pragma unroll
        for (int nt = 0; nt < 4; ++nt) {
            int c = nt * 8 + tc * 2;
            int r = mrow + tr;
            if (r < NT)
                *(__half2*)(og + (size_t)r * DIMC + c) =
                    __floats2half2_rn(oacc[nt][0], oacc[nt][1]);
            if (r + 8 < NT)
                *(__half2*)(og + (size_t)(r + 8) * DIMC + c) =
                    __floats2half2_rn(oacc[nt][2], oacc[nt][3]);
        }
    }
}

// ===========================================================================
extern "C" void kernel_launch(void* const* d_in, const int* in_sizes, int n_in,
                              void* d_out, int out_size)
{
    const float* x      = (const float*)d_in[0];
    const float* mask   = (const float*)d_in[1];
    const float* qkv_w  = (const float*)d_in[2];
    const float* qkv_b  = (const float*)d_in[3];
    const float* proj_w = (const float*)d_in[4];
    const float* proj_b = (const float*)d_in[5];
    const float* btab   = (const float*)d_in[6];
    float* out = (float*)d_out;

    const int B_ = in_sizes[0] / (NT * DIMC);   // 4096
    const int nW = in_sizes[1] / (NT * NT);     // 64
    const int M  = B_ * NT;                     // 200704

    __half *xh, *qkvh, *oh, *wq, *wp;
    cudaGetSymbolAddress((void**)&xh,   g_Xh);
    cudaGetSymbolAddress((void**)&qkvh, g_QKV);
    cudaGetSymbolAddress((void**)&oh,   g_Oh);
    cudaGetSymbolAddress((void**)&wq,   g_Wq);
    cudaGetSymbolAddress((void**)&wp,   g_Wp);

    static int smem_set = 0;
    if (!smem_set) {
        cudaFuncSetAttribute(gemmH<true, 768>,  cudaFuncAttributeMaxDynamicSharedMemorySize, GSMEMH);
        cudaFuncSetAttribute(gemmH<false, 256>, cudaFuncAttributeMaxDynamicSharedMemorySize, GSMEMH);
        smem_set = 1;
    }

    // 1) operand prep: fp32 -> fp16 + combined bias/mask table
    convX<<<(M * DIMC) / 1024, 256>>>((const float4*)x, (__half2*)xh);
    convW<<<256, 256>>>((const float4*)qkv_w, (const float4*)proj_w,
                        (__half2*)wq, (__half2*)wp);
    prepBM<<<dim3(NH, nW), 256>>>(mask, btab);

    // 2) QKV = Xh @ Wq^T + b  (q pre-scaled, fp16 out)
    gemmH<true, 768><<<dim3(6, M / 128), 256, GSMEMH>>>(xh, wq, qkv_b, qkvh);

    // 3) windowed attention per (head, window)
    attnH<<<dim3(NH, B_), 128>>>(qkvh, oh, nW);

    // 4) out = O @ Wp^T + b (fp32 out)
    gemmH<false, 256><<<dim3(2, M / 128), 256, GSMEMH>>>(oh, wp, proj_b, out);
}

// round 7
// speedup vs baseline: 3.1493x; 1.0528x over previous
#include <cuda_runtime.h>
#include <cuda_fp16.h>
#include <cstdint>

#define NT     49
#define DIMC   256
#define NH     8
#define HD     32
#define QSCALE 0.17677669529663687f   // 32^-0.5
#define MAXB   4096
#define MAXW   64

// ------------------------- global scratch ---------------------------------
__device__ __half g_Xh [(size_t)MAXB * NT * DIMC];        // fp16 x
__device__ __half g_QKV[(size_t)MAXB * NT * 3 * DIMC];    // fp16 qkv activations
__device__ __half g_Oh [(size_t)MAXB * NT * DIMC];        // fp16 attention out
__device__ __half g_Wq [3 * DIMC * DIMC];                 // fp16 qkv_w
__device__ __half g_Wp [DIMC * DIMC];                     // fp16 proj_w
__device__ float  g_BM [(size_t)MAXW * NH * NT * 56];     // bias+mask, pad=-1e30

// ---------------------------------------------------------------------------
__device__ __forceinline__ void cpa16(void* smem_dst, const void* gsrc) {
    unsigned d = (unsigned)__cvta_generic_to_shared(smem_dst);
    asm volatile("cp.async.cg.shared.global [%0], [%1], 16;" :: "r"(d), "l"(gsrc));
}

__device__ __forceinline__ void mma16(float* c,
                                      uint32_t a0, uint32_t a1, uint32_t a2, uint32_t a3,
                                      uint32_t b0, uint32_t b1) {
    asm volatile(
        "mma.sync.aligned.m16n8k16.row.col.f32.f16.f16.f32 "
        "{%0,%1,%2,%3}, {%4,%5,%6,%7}, {%8,%9}, {%0,%1,%2,%3};"
        : "+f"(c[0]), "+f"(c[1]), "+f"(c[2]), "+f"(c[3])
        : "r"(a0), "r"(a1), "r"(a2), "r"(a3), "r"(b0), "r"(b1));
}

__device__ __forceinline__ void ldsm4(uint32_t& r0, uint32_t& r1,
                                      uint32_t& r2, uint32_t& r3, uint32_t addr) {
    asm volatile("ldmatrix.sync.aligned.m8n8.x4.shared.b16 {%0,%1,%2,%3}, [%4];"
                 : "=r"(r0), "=r"(r1), "=r"(r2), "=r"(r3) : "r"(addr));
}

__device__ __forceinline__ void ldsm4t(uint32_t& r0, uint32_t& r1,
                                       uint32_t& r2, uint32_t& r3, uint32_t addr) {
    asm volatile("ldmatrix.sync.aligned.m8n8.x4.trans.shared.b16 {%0,%1,%2,%3}, [%4];"
                 : "=r"(r0), "=r"(r1), "=r"(r2), "=r"(r3) : "r"(addr));
}

// ===========================================================================
// prep kernels: fp32 -> fp16 conversion + bias/mask table
// ===========================================================================
__global__ void convX(const float4* __restrict__ src, __half2* __restrict__ dst) {
    size_t i = (size_t)blockIdx.x * 256 + threadIdx.x;
    float4 v = src[i];
    dst[2 * i]     = __floats2half2_rn(v.x, v.y);
    dst[2 * i + 1] = __floats2half2_rn(v.z, v.w);
}

__global__ void convW(const float4* __restrict__ qw, const float4* __restrict__ pw,
                      __half2* __restrict__ qwt, __half2* __restrict__ pwt) {
    int i = blockIdx.x * 256 + threadIdx.x;          // 65536 threads
    if (i < 49152) {
        float4 v = qw[i];
        qwt[2 * i]     = __floats2half2_rn(v.x, v.y);
        qwt[2 * i + 1] = __floats2half2_rn(v.z, v.w);
    } else {
        int j = i - 49152;
        float4 v = pw[j];
        pwt[2 * j]     = __floats2half2_rn(v.x, v.y);
        pwt[2 * j + 1] = __floats2half2_rn(v.z, v.w);
    }
}

__global__ void prepBM(const float* __restrict__ mask,
                       const float* __restrict__ btab) {
    const int h = blockIdx.x, w = blockIdx.y;
    float* dst = g_BM + ((size_t)(w * NH + h) * NT) * 56;
    const float* mg = mask + (size_t)w * NT * NT;
    for (int i = threadIdx.x; i < NT * 56; i += 256) {
        int r = i / 56, c = i - r * 56;
        float v = -1e30f;
        if (c < NT) {
            int ri = r / 7, rc = r - ri * 7;
            int cj = c / 7, cc = c - cj * 7;
            int rel = (ri - cj + 6) * 13 + (rc - cc + 6);
            v = __ldg(btab + rel * 8 + h) + __ldg(mg + r * NT + c);
        }
        dst[i] = v;
    }
}

// ===========================================================================
// fp16 GEMM: C[M,NC] = A[M,256] @ Bw[NC,256]^T (+bias).
// 128x128 CTA tile, K chunks of 64 halves, 3-stage cp.async ring (one
// __syncthreads per chunk), ldmatrix + HMMA.16816.
// ===========================================================================
#define GSTR    72                 // padded smem row stride (halves)
#define GTILE_H (128 * GSTR)       // halves per tile buffer (A or B)
#define STAGE_H (2 * GTILE_H)      // halves per stage (A + B)
#define GSMEMH  (3 * STAGE_H * 2)  // bytes: 3 stages = 110592

__device__ __forceinline__ void stageH(__half* st, const __half* Ag, const __half* Bg,
                                       int ch, int tid) {
    #pragma unroll
    for (int t = 0; t < 8; ++t) {
        int idx = tid + t * 256;            // 0..2047
        int tensor = idx >> 10;             // 0 = A, 1 = B
        int r  = (idx >> 3) & 127;
        int c8 = idx & 7;
        const __half* src = (tensor ? Bg : Ag) + (size_t)r * 256 + ch * 64 + c8 * 8;
        cpa16(st + tensor * GTILE_H + r * GSTR + c8 * 8, src);
    }
    asm volatile("cp.async.commit_group;" ::: "memory");
}

template<bool QKVEPI, int NC>
__global__ __launch_bounds__(256, 2)
void gemmH(const __half* __restrict__ A, const __half* __restrict__ Bw,
           const float* __restrict__ bias, void* __restrict__ Cout)
{
    extern __shared__ __half smh[];
    const int tid  = threadIdx.x;
    const int lane = tid & 31;
    const int wid  = tid >> 5;
    const int tr = lane >> 2, tc = lane & 3;
    const int nt = blockIdx.x, mt = blockIdx.y;
    const int mw = wid & 1;        // 64-row half of tile
    const int nw = wid >> 1;       // 32-col strip

    const __half* Ag = A  + (size_t)(mt * 128) * 256;
    const __half* Bg = Bw + (size_t)(nt * 128) * 256;

    // ldmatrix lane-address components
    const int g8   = lane >> 3;
    const int arow = (lane & 7) + ((g8 & 1) << 3);
    const int acol = (g8 >> 1) << 3;
    const int brow = (lane & 7) + ((g8 >> 1) << 3);
    const int bcol = (g8 & 1) << 3;

    const uint32_t sb = (uint32_t)__cvta_generic_to_shared(smh);

    float acc[4][4][4];
    #pragma unroll
    for (int mi = 0; mi < 4; ++mi)
        #pragma unroll
        for (int ni = 0; ni < 4; ++ni)
            { acc[mi][ni][0]=acc[mi][ni][1]=acc[mi][ni][2]=acc[mi][ni][3]=0.f; }

    // prologue: fill stages 0 and 1
    stageH(smh,           Ag, Bg, 0, tid);
    stageH(smh + STAGE_H, Ag, Bg, 1, tid);

    #pragma unroll
    for (int ch = 0; ch < 4; ++ch) {
        const int buf = ch % 3;
        if (ch < 3) asm volatile("cp.async.wait_group 1;" ::: "memory");
        else        asm volatile("cp.async.wait_group 0;" ::: "memory");
        __syncthreads();
        // refill the buffer consumed in iteration ch-1 (safe after the barrier)
        if (ch < 2)
            stageH(smh + ((ch + 2) % 3) * STAGE_H, Ag, Bg, ch + 2, tid);

        const uint32_t Ab = sb + (uint32_t)(buf * STAGE_H) * 2;
        const uint32_t Bb = Ab + GTILE_H * 2;
        #pragma unroll
        for (int kk = 0; kk < 4; ++kk) {
            uint32_t a[4][4];
            #pragma unroll
            for (int mi = 0; mi < 4; ++mi)
                ldsm4(a[mi][0], a[mi][1], a[mi][2], a[mi][3],
                      Ab + (uint32_t)((mw * 64 + mi * 16 + arow) * GSTR + kk * 16 + acol) * 2);
            uint32_t bf[4][2];
            #pragma unroll
            for (int p = 0; p < 2; ++p) {
                uint32_t r0, r1, r2, r3;
                ldsm4(r0, r1, r2, r3,
                      Bb + (uint32_t)((nw * 32 + p * 16 + brow) * GSTR + kk * 16 + bcol) * 2);
                bf[2 * p][0] = r0; bf[2 * p][1] = r1;
                bf[2 * p + 1][0] = r2; bf[2 * p + 1][1] = r3;
            }
            #pragma unroll
            for (int mi = 0; mi < 4; ++mi)
                #pragma unroll
                for (int ni = 0; ni < 4; ++ni)
                    mma16(acc[mi][ni], a[mi][0], a[mi][1], a[mi][2], a[mi][3],
                          bf[ni][0], bf[ni][1]);
        }
    }

    // epilogue
    #pragma unroll
    for (int mi = 0; mi < 4; ++mi) {
        #pragma unroll
        for (int ni = 0; ni < 4; ++ni) {
            int row = mt * 128 + mw * 64 + mi * 16 + tr;
            int col = nt * 128 + nw * 32 + ni * 8 + tc * 2;
            float b0 = __ldg(bias + col), b1 = __ldg(bias + col + 1);
            float v00 = acc[mi][ni][0] + b0, v01 = acc[mi][ni][1] + b1;
            float v10 = acc[mi][ni][2] + b0, v11 = acc[mi][ni][3] + b1;
            if (QKVEPI) {
                if (col < 256) { v00 *= QSCALE; v01 *= QSCALE; v10 *= QSCALE; v11 *= QSCALE; }
                __half* Ch = (__half*)Cout;
                *(__half2*)(Ch + (size_t)row * NC + col)       = __floats2half2_rn(v00, v01);
                *(__half2*)(Ch + (size_t)(row + 8) * NC + col) = __floats2half2_rn(v10, v11);
            } else {
                float* Cf = (float*)Cout;
                *(float2*)(Cf + (size_t)row * NC + col)       = make_float2(v00, v01);
                *(float2*)(Cf + (size_t)(row + 8) * NC + col) = make_float2(v10, v11);
            }
        }
    }
}

// ===========================================================================
// fp16 attention: CTA = (head, window), 128 threads, ldmatrix + HMMA.
// ===========================================================================
#define AQS 0                      // [64][40] halves
#define AKS (64 * 40)
#define AVS (2 * 64 * 40)
#define APS (3 * 64 * 40)          // P: [64][72]
#define ATT_H (APS + 64 * 72)      // 12288 halves = 24576 B

__global__ __launch_bounds__(128, 5)
void attnH(const __half* __restrict__ qkv, __half* __restrict__ O, int nW)
{
    __shared__ __half sh[ATT_H];
    const int tid  = threadIdx.x;
    const int lane = tid & 31;
    const int wid  = tid >> 5;
    const int h = blockIdx.x;
    const int b = blockIdx.y;
    const int w = b % nW;
    const int tr = lane >> 2, tc = lane & 3;
    const uint32_t sb = (uint32_t)__cvta_generic_to_shared(sh);

    // zero K,V pad rows 49..63 (600 halves each, contiguous)
    {
        uint32_t* zk = (uint32_t*)(sh + AKS + NT * 40);
        uint32_t* zv = (uint32_t*)(sh + AVS + NT * 40);
        for (int i = tid; i < 300; i += 128) { zk[i] = 0u; zv[i] = 0u; }
    }
    // stage q/k/v head slices (49 rows x 32 halves each)
    {
        const __half* base = qkv + (size_t)b * NT * 768 + h * 32;
        for (int i = tid; i < NT * 4; i += 128) {
            int r = i >> 2, c = (i & 3) * 8;
            const __half* g = base + (size_t)r * 768 + c;
            cpa16(sh + AQS + r * 40 + c, g);
            cpa16(sh + AKS + r * 40 + c, g + 256);
            cpa16(sh + AVS + r * 40 + c, g + 512);
        }
        asm volatile("cp.async.commit_group;" ::: "memory");
        asm volatile("cp.async.wait_group 0;" ::: "memory");
    }
    __syncthreads();

    const int mrow = wid * 16;
    const int g8   = lane >> 3;
    const int arow = (lane & 7) + ((g8 & 1) << 3);
    const int acol = (g8 >> 1) << 3;
    const int brow = (lane & 7) + ((g8 >> 1) << 3);
    const int bcol = (g8 & 1) << 3;

    // ---- S = q @ k^T  (q pre-scaled; K=32 -> 2 k16 steps; 7 n-tiles) ----
    float sacc[7][4];
    #pragma unroll
    for (int t = 0; t < 7; ++t) { sacc[t][0]=sacc[t][1]=sacc[t][2]=sacc[t][3]=0.f; }
    {
        uint32_t qa[2][4];
        #pragma unroll
        for (int kk = 0; kk < 2; ++kk)
            ldsm4(qa[kk][0], qa[kk][1], qa[kk][2], qa[kk][3],
                  sb + (uint32_t)((AQS + (mrow + arow) * 40 + kk * 16 + acol)) * 2);
        #pragma unroll
        for (int kk = 0; kk < 2; ++kk) {
            #pragma unroll
            for (int p = 0; p < 4; ++p) {
                uint32_t r0, r1, r2, r3;
                ldsm4(r0, r1, r2, r3,
                      sb + (uint32_t)((AKS + (p * 16 + brow) * 40 + kk * 16 + bcol)) * 2);
                mma16(sacc[2 * p], qa[kk][0], qa[kk][1], qa[kk][2], qa[kk][3], r0, r1);
                if (p < 3)
                    mma16(sacc[2 * p + 1], qa[kk][0], qa[kk][1], qa[kk][2], qa[kk][3], r2, r3);
            }
        }
    }

    // ---- register softmax + P (half) smem write; zero pad cols 56..63 ----
    {
        const float* bmb = g_BM + ((size_t)(w * NH + h) * NT) * 56;
        #pragma unroll
        for (int g2 = 0; g2 < 2; ++g2) {
            int r  = mrow + tr + 8 * g2;
            int rb = (r < NT) ? r : NT - 1;
            const float* bmr = bmb + (size_t)rb * 56 + tc * 2;
            float v[7][2];
            float m = -3.4e38f;
            #pragma unroll
            for (int nt = 0; nt < 7; ++nt) {
                float2 bm2 = *(const float2*)(bmr + nt * 8);
                v[nt][0] = sacc[nt][2 * g2]     + bm2.x;
                v[nt][1] = sacc[nt][2 * g2 + 1] + bm2.y;
                m = fmaxf(m, fmaxf(v[nt][0], v[nt][1]));
            }
            m = fmaxf(m, __shfl_xor_sync(0xffffffffu, m, 1));
            m = fmaxf(m, __shfl_xor_sync(0xffffffffu, m, 2));
            float s = 0.f;
            #pragma unroll
            for (int nt = 0; nt < 7; ++nt) {
                v[nt][0] = __expf(v[nt][0] - m);
                v[nt][1] = __expf(v[nt][1] - m);
                s += v[nt][0] + v[nt][1];
            }
            s += __shfl_xor_sync(0xffffffffu, s, 1);
            s += __shfl_xor_sync(0xffffffffu, s, 2);
            float inv = 1.0f / s;
            __half* pr = sh + APS + r * 72 + tc * 2;
            #pragma unroll
            for (int nt = 0; nt < 7; ++nt)
                *(__half2*)(pr + nt * 8) = __floats2half2_rn(v[nt][0] * inv, v[nt][1] * inv);
            *(__half2*)(pr + 56) = __float2half2_rn(0.f);   // cols 56..63
        }
    }
    __syncwarp();   // this warp's PV reads only its own P rows

    // ---- O = P @ v  (K=64 padded -> 4 k16 steps; V via trans ldmatrix) ----
    {
        float oacc[4][4];
        #pragma unroll
        for (int t = 0; t < 4; ++t) { oacc[t][0]=oacc[t][1]=oacc[t][2]=oacc[t][3]=0.f; }
        #pragma unroll
        for (int kk = 0; kk < 4; ++kk) {
            uint32_t pa0, pa1, pa2, pa3;
            ldsm4(pa0, pa1, pa2, pa3,
                  sb + (uint32_t)((APS + (mrow + arow) * 72 + kk * 16 + acol)) * 2);
            #pragma unroll
            for (int q = 0; q < 2; ++q) {
                uint32_t r0, r1, r2, r3;
                ldsm4t(r0, r1, r2, r3,
                       sb + (uint32_t)((AVS + (kk * 16 + (lane & 7) + ((g8 & 1) << 3)) * 40
                                        + q * 16 + ((g8 >> 1) << 3))) * 2);
                mma16(oacc[2 * q],     pa0, pa1, pa2, pa3, r0, r1);
                mma16(oacc[2 * q + 1], pa0, pa1, pa2, pa3, r2, r3);
            }
        }
        __half* og = O + (size_t)b * NT * DIMC + h * HD;
        #pragma unroll
        for (int nt = 0; nt < 4; ++nt) {
            int c = nt * 8 + tc * 2;
            int r = mrow + tr;
            if (r < NT)
                *(__half2*)(og + (size_t)r * DIMC + c) =
                    __floats2half2_rn(oacc[nt][0], oacc[nt][1]);
            if (r + 8 < NT)
                *(__half2*)(og + (size_t)(r + 8) * DIMC + c) =
                    __floats2half2_rn(oacc[nt][2], oacc[nt][3]);
        }
    }
}

// ===========================================================================
extern "C" void kernel_launch(void* const* d_in, const int* in_sizes, int n_in,
                              void* d_out, int out_size)
{
    const float* x      = (const float*)d_in[0];
    const float* mask   = (const float*)d_in[1];
    const float* qkv_w  = (const float*)d_in[2];
    const float* qkv_b  = (const float*)d_in[3];
    const float* proj_w = (const float*)d_in[4];
    const float* proj_b = (const float*)d_in[5];
    const float* btab   = (const float*)d_in[6];
    float* out = (float*)d_out;

    const int B_ = in_sizes[0] / (NT * DIMC);   // 4096
    const int nW = in_sizes[1] / (NT * NT);     // 64
    const int M  = B_ * NT;                     // 200704

    __half *xh, *qkvh, *oh, *wq, *wp;
    cudaGetSymbolAddress((void**)&xh,   g_Xh);
    cudaGetSymbolAddress((void**)&qkvh, g_QKV);
    cudaGetSymbolAddress((void**)&oh,   g_Oh);
    cudaGetSymbolAddress((void**)&wq,   g_Wq);
    cudaGetSymbolAddress((void**)&wp,   g_Wp);

    static int smem_set = 0;
    if (!smem_set) {
        cudaFuncSetAttribute(gemmH<true, 768>,  cudaFuncAttributeMaxDynamicSharedMemorySize, GSMEMH);
        cudaFuncSetAttribute(gemmH<false, 256>, cudaFuncAttributeMaxDynamicSharedMemorySize, GSMEMH);
        smem_set = 1;
    }

    // 1) operand prep: fp32 -> fp16 + combined bias/mask table
    convX<<<(M * DIMC) / 1024, 256>>>((const float4*)x, (__half2*)xh);
    convW<<<256, 256>>>((const float4*)qkv_w, (const float4*)proj_w,
                        (__half2*)wq, (__half2*)wp);
    prepBM<<<dim3(NH, nW), 256>>>(mask, btab);

    // 2) QKV = Xh @ Wq^T + b  (q pre-scaled, fp16 out)
    gemmH<true, 768><<<dim3(6, M / 128), 256, GSMEMH>>>(xh, wq, qkv_b, qkvh);

    // 3) windowed attention per (head, window)
    attnH<<<dim3(NH, B_), 128>>>(qkvh, oh, nW);

    // 4) out = O @ Wp^T + b (fp32 out)
    gemmH<false, 256><<<dim3(2, M / 128), 256, GSMEMH>>>(oh, wp, proj_b, out);
}

// round 8
// speedup vs baseline: 3.2022x; 1.0168x over previous
#include <cuda_runtime.h>
#include <cuda_fp16.h>
#include <cstdint>

#define NT     49
#define DIMC   256
#define NH     8
#define HD     32
#define QSCALE 0.17677669529663687f   // 32^-0.5
#define MAXB   4096
#define MAXW   64

// ------------------------- global scratch ---------------------------------
__device__ __half g_Xh [(size_t)MAXB * NT * DIMC];        // fp16 x
__device__ __half g_QKV[(size_t)MAXB * NT * 3 * DIMC];    // fp16 qkv activations
__device__ __half g_Oh [(size_t)MAXB * NT * DIMC];        // fp16 attention out
__device__ __half g_Wq [3 * DIMC * DIMC];                 // fp16 qkv_w
__device__ __half g_Wp [DIMC * DIMC];                     // fp16 proj_w
__device__ float  g_BM [(size_t)MAXW * NH * NT * 56];     // bias+mask, pad=-1e30

// ---------------------------------------------------------------------------
__device__ __forceinline__ void cpa16(void* smem_dst, const void* gsrc) {
    unsigned d = (unsigned)__cvta_generic_to_shared(smem_dst);
    asm volatile("cp.async.cg.shared.global [%0], [%1], 16;" :: "r"(d), "l"(gsrc));
}

__device__ __forceinline__ void mma16(float* c,
                                      uint32_t a0, uint32_t a1, uint32_t a2, uint32_t a3,
                                      uint32_t b0, uint32_t b1) {
    asm volatile(
        "mma.sync.aligned.m16n8k16.row.col.f32.f16.f16.f32 "
        "{%0,%1,%2,%3}, {%4,%5,%6,%7}, {%8,%9}, {%0,%1,%2,%3};"
        : "+f"(c[0]), "+f"(c[1]), "+f"(c[2]), "+f"(c[3])
        : "r"(a0), "r"(a1), "r"(a2), "r"(a3), "r"(b0), "r"(b1));
}

__device__ __forceinline__ void ldsm4(uint32_t& r0, uint32_t& r1,
                                      uint32_t& r2, uint32_t& r3, uint32_t addr) {
    asm volatile("ldmatrix.sync.aligned.m8n8.x4.shared.b16 {%0,%1,%2,%3}, [%4];"
                 : "=r"(r0), "=r"(r1), "=r"(r2), "=r"(r3) : "r"(addr));
}

__device__ __forceinline__ void ldsm4t(uint32_t& r0, uint32_t& r1,
                                       uint32_t& r2, uint32_t& r3, uint32_t addr) {
    asm volatile("ldmatrix.sync.aligned.m8n8.x4.trans.shared.b16 {%0,%1,%2,%3}, [%4];"
                 : "=r"(r0), "=r"(r1), "=r"(r2), "=r"(r3) : "r"(addr));
}

// ===========================================================================
// prep kernels: fp32 -> fp16 conversion + bias/mask table
// ===========================================================================
__global__ void convX(const float4* __restrict__ src, __half2* __restrict__ dst) {
    size_t i = (size_t)blockIdx.x * 256 + threadIdx.x;
    float4 v = src[i];
    dst[2 * i]     = __floats2half2_rn(v.x, v.y);
    dst[2 * i + 1] = __floats2half2_rn(v.z, v.w);
}

__global__ void convW(const float4* __restrict__ qw, const float4* __restrict__ pw,
                      __half2* __restrict__ qwt, __half2* __restrict__ pwt) {
    int i = blockIdx.x * 256 + threadIdx.x;          // 65536 threads
    if (i < 49152) {
        float4 v = qw[i];
        qwt[2 * i]     = __floats2half2_rn(v.x, v.y);
        qwt[2 * i + 1] = __floats2half2_rn(v.z, v.w);
    } else {
        int j = i - 49152;
        float4 v = pw[j];
        pwt[2 * j]     = __floats2half2_rn(v.x, v.y);
        pwt[2 * j + 1] = __floats2half2_rn(v.z, v.w);
    }
}

__global__ void prepBM(const float* __restrict__ mask,
                       const float* __restrict__ btab) {
    const int h = blockIdx.x, w = blockIdx.y;
    float* dst = g_BM + ((size_t)(w * NH + h) * NT) * 56;
    const float* mg = mask + (size_t)w * NT * NT;
    for (int i = threadIdx.x; i < NT * 56; i += 256) {
        int r = i / 56, c = i - r * 56;
        float v = -1e30f;
        if (c < NT) {
            int ri = r / 7, rc = r - ri * 7;
            int cj = c / 7, cc = c - cj * 7;
            int rel = (ri - cj + 6) * 13 + (rc - cc + 6);
            v = __ldg(btab + rel * 8 + h) + __ldg(mg + r * NT + c);
        }
        dst[i] = v;
    }
}

// ===========================================================================
// fp16 GEMM: C[M,NC] = A[M,256] @ Bw[NC,256]^T (+bias).
// 128x128 CTA tile, 128 threads (4 warps, 64x64 warp tiles), K chunks of 64,
// 3-stage cp.async ring, ldmatrix + HMMA.16816.
// 0.25 LDSM per HMMA (was 0.375) -> smem-crossbar relief.
// ===========================================================================
#define GSTR    72                 // padded smem row stride (halves)
#define GTILE_H (128 * GSTR)       // halves per tile buffer (A or B)
#define STAGE_H (2 * GTILE_H)      // halves per stage (A + B)
#define GSMEMH  (3 * STAGE_H * 2)  // bytes: 3 stages = 110592

__device__ __forceinline__ void stageH(__half* st, const __half* Ag, const __half* Bg,
                                       int ch, int tid) {
    #pragma unroll
    for (int t = 0; t < 16; ++t) {
        int idx = tid + t * 128;            // 0..2047
        int tensor = idx >> 10;             // 0 = A, 1 = B
        int r  = (idx >> 3) & 127;
        int c8 = idx & 7;
        const __half* src = (tensor ? Bg : Ag) + (size_t)r * 256 + ch * 64 + c8 * 8;
        cpa16(st + tensor * GTILE_H + r * GSTR + c8 * 8, src);
    }
    asm volatile("cp.async.commit_group;" ::: "memory");
}

template<bool QKVEPI, int NC>
__global__ __launch_bounds__(128, 2)
void gemmH(const __half* __restrict__ A, const __half* __restrict__ Bw,
           const float* __restrict__ bias, void* __restrict__ Cout)
{
    extern __shared__ __half smh[];
    const int tid  = threadIdx.x;
    const int lane = tid & 31;
    const int wid  = tid >> 5;            // 0..3
    const int tr = lane >> 2, tc = lane & 3;
    const int nt = blockIdx.x, mt = blockIdx.y;
    const int mw = wid & 1;               // 64-row half of tile
    const int nw = wid >> 1;              // 64-col half of tile

    const __half* Ag = A  + (size_t)(mt * 128) * 256;
    const __half* Bg = Bw + (size_t)(nt * 128) * 256;

    // ldmatrix lane-address components
    const int g8   = lane >> 3;
    const int arow = (lane & 7) + ((g8 & 1) << 3);
    const int acol = (g8 >> 1) << 3;
    const int brow = (lane & 7) + ((g8 >> 1) << 3);
    const int bcol = (g8 & 1) << 3;

    const uint32_t sb = (uint32_t)__cvta_generic_to_shared(smh);

    float acc[4][8][4];
    #pragma unroll
    for (int mi = 0; mi < 4; ++mi)
        #pragma unroll
        for (int ni = 0; ni < 8; ++ni)
            { acc[mi][ni][0]=acc[mi][ni][1]=acc[mi][ni][2]=acc[mi][ni][3]=0.f; }

    // prologue: fill stages 0 and 1
    stageH(smh,           Ag, Bg, 0, tid);
    stageH(smh + STAGE_H, Ag, Bg, 1, tid);

    #pragma unroll
    for (int ch = 0; ch < 4; ++ch) {
        const int buf = ch % 3;
        if (ch < 3) asm volatile("cp.async.wait_group 1;" ::: "memory");
        else        asm volatile("cp.async.wait_group 0;" ::: "memory");
        __syncthreads();
        // refill the buffer consumed in iteration ch-1 (safe after the barrier)
        if (ch < 2)
            stageH(smh + ((ch + 2) % 3) * STAGE_H, Ag, Bg, ch + 2, tid);

        const uint32_t Ab = sb + (uint32_t)(buf * STAGE_H) * 2;
        const uint32_t Bb = Ab + GTILE_H * 2;
        #pragma unroll
        for (int kk = 0; kk < 4; ++kk) {
            uint32_t a[4][4];
            #pragma unroll
            for (int mi = 0; mi < 4; ++mi)
                ldsm4(a[mi][0], a[mi][1], a[mi][2], a[mi][3],
                      Ab + (uint32_t)((mw * 64 + mi * 16 + arow) * GSTR + kk * 16 + acol) * 2);
            uint32_t bf[8][2];
            #pragma unroll
            for (int p = 0; p < 4; ++p) {
                uint32_t r0, r1, r2, r3;
                ldsm4(r0, r1, r2, r3,
                      Bb + (uint32_t)((nw * 64 + p * 16 + brow) * GSTR + kk * 16 + bcol) * 2);
                bf[2 * p][0] = r0; bf[2 * p][1] = r1;
                bf[2 * p + 1][0] = r2; bf[2 * p + 1][1] = r3;
            }
            #pragma unroll
            for (int mi = 0; mi < 4; ++mi)
                #pragma unroll
                for (int ni = 0; ni < 8; ++ni)
                    mma16(acc[mi][ni], a[mi][0], a[mi][1], a[mi][2], a[mi][3],
                          bf[ni][0], bf[ni][1]);
        }
    }

    // epilogue
    const float sc = (QKVEPI && nt < 2) ? QSCALE : 1.0f;
    #pragma unroll
    for (int ni = 0; ni < 8; ++ni) {
        int col = nt * 128 + nw * 64 + ni * 8 + tc * 2;
        float b0 = __ldg(bias + col), b1 = __ldg(bias + col + 1);
        #pragma unroll
        for (int mi = 0; mi < 4; ++mi) {
            int row = mt * 128 + mw * 64 + mi * 16 + tr;
            float v00 = acc[mi][ni][0] + b0, v01 = acc[mi][ni][1] + b1;
            float v10 = acc[mi][ni][2] + b0, v11 = acc[mi][ni][3] + b1;
            if (QKVEPI) {
                v00 *= sc; v01 *= sc; v10 *= sc; v11 *= sc;
                __half* Ch = (__half*)Cout;
                *(__half2*)(Ch + (size_t)row * NC + col)       = __floats2half2_rn(v00, v01);
                *(__half2*)(Ch + (size_t)(row + 8) * NC + col) = __floats2half2_rn(v10, v11);
            } else {
                float* Cf = (float*)Cout;
                *(float2*)(Cf + (size_t)row * NC + col)       = make_float2(v00, v01);
                *(float2*)(Cf + (size_t)(row + 8) * NC + col) = make_float2(v10, v11);
            }
        }
    }
}

// ===========================================================================
// fp16 attention: CTA = (head, window), 128 threads, ldmatrix + HMMA.
// ===========================================================================
#define AQS 0                      // [64][40] halves
#define AKS (64 * 40)
#define AVS (2 * 64 * 40)
#define APS (3 * 64 * 40)          // P: [64][72]
#define ATT_H (APS + 64 * 72)      // 12288 halves = 24576 B

__global__ __launch_bounds__(128, 5)
void attnH(const __half* __restrict__ qkv, __half* __restrict__ O, int nW)
{
    __shared__ __half sh[ATT_H];
    const int tid  = threadIdx.x;
    const int lane = tid & 31;
    const int wid  = tid >> 5;
    const int h = blockIdx.x;
    const int b = blockIdx.y;
    const int w = b % nW;
    const int tr = lane >> 2, tc = lane & 3;
    const uint32_t sb = (uint32_t)__cvta_generic_to_shared(sh);

    // zero K,V pad rows 49..63 (600 halves each, contiguous)
    {
        uint32_t* zk = (uint32_t*)(sh + AKS + NT * 40);
        uint32_t* zv = (uint32_t*)(sh + AVS + NT * 40);
        for (int i = tid; i < 300; i += 128) { zk[i] = 0u; zv[i] = 0u; }
    }
    // stage q/k/v head slices (49 rows x 32 halves each)
    {
        const __half* base = qkv + (size_t)b * NT * 768 + h * 32;
        for (int i = tid; i < NT * 4; i += 128) {
            int r = i >> 2, c = (i & 3) * 8;
            const __half* g = base + (size_t)r * 768 + c;
            cpa16(sh + AQS + r * 40 + c, g);
            cpa16(sh + AKS + r * 40 + c, g + 256);
            cpa16(sh + AVS + r * 40 + c, g + 512);
        }
        asm volatile("cp.async.commit_group;" ::: "memory");
        asm volatile("cp.async.wait_group 0;" ::: "memory");
    }
    __syncthreads();

    const int mrow = wid * 16;
    const int g8   = lane >> 3;
    const int arow = (lane & 7) + ((g8 & 1) << 3);
    const int acol = (g8 >> 1) << 3;
    const int brow = (lane & 7) + ((g8 >> 1) << 3);
    const int bcol = (g8 & 1) << 3;

    // ---- S = q @ k^T  (q pre-scaled; K=32 -> 2 k16 steps; 7 n-tiles) ----
    float sacc[7][4];
    #pragma unroll
    for (int t = 0; t < 7; ++t) { sacc[t][0]=sacc[t][1]=sacc[t][2]=sacc[t][3]=0.f; }
    {
        uint32_t qa[2][4];
        #pragma unroll
        for (int kk = 0; kk < 2; ++kk)
            ldsm4(qa[kk][0], qa[kk][1], qa[kk][2], qa[kk][3],
                  sb + (uint32_t)((AQS + (mrow + arow) * 40 + kk * 16 + acol)) * 2);
        #pragma unroll
        for (int kk = 0; kk < 2; ++kk) {
            #pragma unroll
            for (int p = 0; p < 4; ++p) {
                uint32_t r0, r1, r2, r3;
                ldsm4(r0, r1, r2, r3,
                      sb + (uint32_t)((AKS + (p * 16 + brow) * 40 + kk * 16 + bcol)) * 2);
                mma16(sacc[2 * p], qa[kk][0], qa[kk][1], qa[kk][2], qa[kk][3], r0, r1);
                if (p < 3)
                    mma16(sacc[2 * p + 1], qa[kk][0], qa[kk][1], qa[kk][2], qa[kk][3], r2, r3);
            }
        }
    }

    // ---- register softmax + P (half) smem write; zero pad cols 56..63 ----
    {
        const float* bmb = g_BM + ((size_t)(w * NH + h) * NT) * 56;
        #pragma unroll
        for (int g2 = 0; g2 < 2; ++g2) {
            int r  = mrow + tr + 8 * g2;
            int rb = (r < NT) ? r : NT - 1;
            const float* bmr = bmb + (size_t)rb * 56 + tc * 2;
            float v[7][2];
            float m = -3.4e38f;
            #pragma unroll
            for (int nt = 0; nt < 7; ++nt) {
                float2 bm2 = *(const float2*)(bmr + nt * 8);
                v[nt][0] = sacc[nt][2 * g2]     + bm2.x;
                v[nt][1] = sacc[nt][2 * g2 + 1] + bm2.y;
                m = fmaxf(m, fmaxf(v[nt][0], v[nt][1]));
            }
            m = fmaxf(m, __shfl_xor_sync(0xffffffffu, m, 1));
            m = fmaxf(m, __shfl_xor_sync(0xffffffffu, m, 2));
            float s = 0.f;
            #pragma unroll
            for (int nt = 0; nt < 7; ++nt) {
                v[nt][0] = __expf(v[nt][0] - m);
                v[nt][1] = __expf(v[nt][1] - m);
                s += v[nt][0] + v[nt][1];
            }
            s += __shfl_xor_sync(0xffffffffu, s, 1);
            s += __shfl_xor_sync(0xffffffffu, s, 2);
            float inv = 1.0f / s;
            __half* pr = sh + APS + r * 72 + tc * 2;
            #pragma unroll
            for (int nt = 0; nt < 7; ++nt)
                *(__half2*)(pr + nt * 8) = __floats2half2_rn(v[nt][0] * inv, v[nt][1] * inv);
            *(__half2*)(pr + 56) = __float2half2_rn(0.f);   // cols 56..63
        }
    }
    __syncwarp();   // this warp's PV reads only its own P rows

    // ---- O = P @ v  (K=64 padded -> 4 k16 steps; V via trans ldmatrix) ----
    {
        float oacc[4][4];
        #pragma unroll
        for (int t = 0; t < 4; ++t) { oacc[t][0]=oacc[t][1]=oacc[t][2]=oacc[t][3]=0.f; }
        #pragma unroll
        for (int kk = 0; kk < 4; ++kk) {
            uint32_t pa0, pa1, pa2, pa3;
            ldsm4(pa0, pa1, pa2, pa3,
                  sb + (uint32_t)((APS + (mrow + arow) * 72 + kk * 16 + acol)) * 2);
            #pragma unroll
            for (int q = 0; q < 2; ++q) {
                uint32_t r0, r1, r2, r3;
                ldsm4t(r0, r1, r2, r3,
                       sb + (uint32_t)((AVS + (kk * 16 + (lane & 7) + ((g8 & 1) << 3)) * 40
                                        + q * 16 + ((g8 >> 1) << 3))) * 2);
                mma16(oacc[2 * q],     pa0, pa1, pa2, pa3, r0, r1);
                mma16(oacc[2 * q + 1], pa0, pa1, pa2, pa3, r2, r3);
            }
        }
        __half* og = O + (size_t)b * NT * DIMC + h * HD;
        #pragma unroll
        for (int nt = 0; nt < 4; ++nt) {
            int c = nt * 8 + tc * 2;
            int r = mrow + tr;
            if (r < NT)
                *(__half2*)(og + (size_t)r * DIMC + c) =
                    __floats2half2_rn(oacc[nt][0], oacc[nt][1]);
            if (r + 8 < NT)
                *(__half2*)(og + (size_t)(r + 8) * DIMC + c) =
                    __floats2half2_rn(oacc[nt][2], oacc[nt][3]);
        }
    }
}

// ===========================================================================
extern "C" void kernel_launch(void* const* d_in, const int* in_sizes, int n_in,
                              void* d_out, int out_size)
{
    const float* x      = (const float*)d_in[0];
    const float* mask   = (const float*)d_in[1];
    const float* qkv_w  = (const float*)d_in[2];
    const float* qkv_b  = (const float*)d_in[3];
    const float* proj_w = (const float*)d_in[4];
    const float* proj_b = (const float*)d_in[5];
    const float* btab   = (const float*)d_in[6];
    float* out = (float*)d_out;

    const int B_ = in_sizes[0] / (NT * DIMC);   // 4096
    const int nW = in_sizes[1] / (NT * NT);     // 64
    const int M  = B_ * NT;                     // 200704

    __half *xh, *qkvh, *oh, *wq, *wp;
    cudaGetSymbolAddress((void**)&xh,   g_Xh);
    cudaGetSymbolAddress((void**)&qkvh, g_QKV);
    cudaGetSymbolAddress((void**)&oh,   g_Oh);
    cudaGetSymbolAddress((void**)&wq,   g_Wq);
    cudaGetSymbolAddress((void**)&wp,   g_Wp);

    static int smem_set = 0;
    if (!smem_set) {
        cudaFuncSetAttribute(gemmH<true, 768>,  cudaFuncAttributeMaxDynamicSharedMemorySize, GSMEMH);
        cudaFuncSetAttribute(gemmH<false, 256>, cudaFuncAttributeMaxDynamicSharedMemorySize, GSMEMH);
        smem_set = 1;
    }

    // 1) operand prep: fp32 -> fp16 + combined bias/mask table
    convX<<<(M * DIMC) / 1024, 256>>>((const float4*)x, (__half2*)xh);
    convW<<<256, 256>>>((const float4*)qkv_w, (const float4*)proj_w,
                        (__half2*)wq, (__half2*)wp);
    prepBM<<<dim3(NH, nW), 256>>>(mask, btab);

    // 2) QKV = Xh @ Wq^T + b  (q pre-scaled, fp16 out)
    gemmH<true, 768><<<dim3(6, M / 128), 128, GSMEMH>>>(xh, wq, qkv_b, qkvh);

    // 3) windowed attention per (head, window)
    attnH<<<dim3(NH, B_), 128>>>(qkvh, oh, nW);

    // 4) out = O @ Wp^T + b (fp32 out)
    gemmH<false, 256><<<dim3(2, M / 128), 128, GSMEMH>>>(oh, wp, proj_b, out);
}